// round 13
// baseline (speedup 1.0000x reference)
#include <cuda_runtime.h>
#include <cuda_bf16.h>
#include <math.h>
#include <stdint.h>

#define BATCH 8192
#define DIN   3200
#define DH    128
#define NEXP  5
#define CHP   24      // channel pitch for pool tiles (48B rows: 16B-aligned, conflict-free)

// ---------------- scratch (static device memory; no allocation) ----------------
__device__ __nv_bfloat16 g_poolt_h[BATCH * 144 * CHP]; // conv1 out hi [B][pos][24]
__device__ __nv_bfloat16 g_poolt_l[BATCH * 144 * CHP]; // conv1 out lo
__device__ float g_feat[BATCH * DIN];                  // conv2 output fp32 (router)
__device__ __nv_bfloat16 g_featbf[BATCH * DIN];        // conv2 output bf16 (gemm1)
__device__ __nv_bfloat16 g_w1t[NEXP * DH * DIN];       // W1e transposed bf16 [5][128][3200]
__device__ __nv_bfloat16 g_w2t[NEXP * DH * DH];        // W2e transposed bf16 [5][g][h]
__device__ float g_wgT[10 * DIN];                      // [Wg|Wglu]^T fp32
__device__ float g_gw  [BATCH * NEXP];                 // routing weights [B,5]
__device__ __nv_bfloat16 g_e1bf[BATCH * NEXP * DH];    // expert layer-1 bf16 [B,640]

// =========================== PTX helpers (baseline ISA only) ====================
__device__ __forceinline__ uint32_t smem_u32(const void* p) {
    uint32_t a;
    asm("{ .reg .u64 t; cvta.to.shared.u64 t, %1; cvt.u32.u64 %0, t; }" : "=r"(a) : "l"(p));
    return a;
}
__device__ __forceinline__ void cp_async16(uint32_t dst, const void* src) {
    asm volatile("cp.async.cg.shared.global [%0], [%1], 16;" :: "r"(dst), "l"(src) : "memory");
}
#define CP_COMMIT() asm volatile("cp.async.commit_group;" ::: "memory")
#define CP_WAIT(n)  asm volatile("cp.async.wait_group %0;" :: "n"(n) : "memory")

__device__ __forceinline__ void ldsm_x4(uint32_t addr, uint32_t& r0, uint32_t& r1,
                                        uint32_t& r2, uint32_t& r3) {
    asm volatile("ldmatrix.sync.aligned.m8n8.x4.shared.b16 {%0,%1,%2,%3}, [%4];"
                 : "=r"(r0), "=r"(r1), "=r"(r2), "=r"(r3) : "r"(addr));
}
__device__ __forceinline__ void mma_bf16(float* d, const uint32_t* a, const uint32_t* b) {
    asm volatile("mma.sync.aligned.m16n8k16.row.col.f32.bf16.bf16.f32 "
                 "{%0,%1,%2,%3}, {%4,%5,%6,%7}, {%8,%9}, {%0,%1,%2,%3};"
                 : "+f"(d[0]), "+f"(d[1]), "+f"(d[2]), "+f"(d[3])
                 : "r"(a[0]), "r"(a[1]), "r"(a[2]), "r"(a[3]), "r"(b[0]), "r"(b[1]));
}
__device__ __forceinline__ uint32_t bf16pack(float a, float b) {
    return (uint32_t)__bfloat16_as_ushort(__float2bfloat16(a)) |
           ((uint32_t)__bfloat16_as_ushort(__float2bfloat16(b)) << 16);
}

// ====== Kernel 1: conv1 (5x5) + ReLU + maxpool — HMMA implicit im2col ===========
// 1 image/CTA, 128 threads (4 warps). A[576 pos][K=32] (taps ky*6+kx, pads 0),
// B[16 ch][32]; 3-pass split-bf16 => fp32-exact conv; pool in smem; out hi/lo.
#define C1_IMG  0
#define C1_B    3200          // B_hi 16x80B=1280, B_lo at +1280 -> ends 5760
#define C1_A    5760          // A_hi 576x80 = 46080
#define C1_ALO  (5760 + 46080)
#define C1_OUT  5760          // fp32 [576][18], overlaps A_hi after MMA
#define C1_SMEM (5760 + 2 * 46080)
__global__ void __launch_bounds__(128)
k_conv1_mma(const float* __restrict__ x,
            const float* __restrict__ w,      // [16][1][5][5]
            const float* __restrict__ bias,   // [16]
            __nv_bfloat16* __restrict__ ph,
            __nv_bfloat16* __restrict__ pl) {
    extern __shared__ __align__(16) unsigned char sm1[];
    uint32_t sb = smem_u32(sm1);
    float* s_img = (float*)sm1;
    int tid = threadIdx.x;
    int wpid = tid >> 5, lane = tid & 31;
    int b = blockIdx.x;

    // load image
    for (int i = tid; i < 784; i += 128) s_img[i] = x[(size_t)b * 784 + i];

    // B fill: [ch][c=ky*6+kx], pads zero, hi+lo planes (640 slots each)
    for (int i = tid; i < 640; i += 128) {
        int ch = i / 40, c = i % 40;
        float v = 0.0f;
        int ky = c / 6, kx = c - ky * 6;
        if (c < 30 && kx < 5) v = w[ch * 25 + ky * 5 + kx];
        __nv_bfloat16 h = __float2bfloat16(v);
        *(__nv_bfloat16*)(sm1 + C1_B + ch * 80 + c * 2) = h;
        *(__nv_bfloat16*)(sm1 + C1_B + 1280 + ch * 80 + c * 2) =
            __float2bfloat16(v - __bfloat162float(h));
    }
    __syncthreads();   // image visible before im2col

    // im2col: pos p -> A[p][ky*6+kx] = img[oy+ky][ox+kx], hi/lo u32-packed
    for (int it = 0; it < 5; it++) {
        int p = tid + it * 128;
        if (p < 576) {
            int oy = p / 24, ox = p - oy * 24;
            uint32_t ah = sb + C1_A  + p * 80;
            uint32_t al = sb + C1_ALO + p * 80;
#pragma unroll
            for (int ky = 0; ky < 5; ky++) {
                const float* src = &s_img[(oy + ky) * 28 + ox];
                float v0 = src[0], v1 = src[1], v2 = src[2], v3 = src[3], v4 = src[4];
                __nv_bfloat16 h0 = __float2bfloat16(v0), h1 = __float2bfloat16(v1),
                              h2 = __float2bfloat16(v2), h3 = __float2bfloat16(v3),
                              h4 = __float2bfloat16(v4);
                uint32_t hp0 = (uint32_t)__bfloat16_as_ushort(h0) |
                               ((uint32_t)__bfloat16_as_ushort(h1) << 16);
                uint32_t hp1 = (uint32_t)__bfloat16_as_ushort(h2) |
                               ((uint32_t)__bfloat16_as_ushort(h3) << 16);
                uint32_t hp2 = (uint32_t)__bfloat16_as_ushort(h4);  // pair (v4, 0)
                uint32_t lp0 = bf16pack(v0 - __bfloat162float(h0), v1 - __bfloat162float(h1));
                uint32_t lp1 = bf16pack(v2 - __bfloat162float(h2), v3 - __bfloat162float(h3));
                uint32_t lp2 = (uint32_t)__bfloat16_as_ushort(
                                   __float2bfloat16(v4 - __bfloat162float(h4)));
                uint32_t off = ky * 12;          // ky*6 elems * 2B
                *(uint32_t*)(sm1 + (ah - sb) + off)     = hp0;
                *(uint32_t*)(sm1 + (ah - sb) + off + 4) = hp1;
                *(uint32_t*)(sm1 + (ah - sb) + off + 8) = hp2;
                *(uint32_t*)(sm1 + (al - sb) + off)     = lp0;
                *(uint32_t*)(sm1 + (al - sb) + off + 4) = lp1;
                *(uint32_t*)(sm1 + (al - sb) + off + 8) = lp2;
            }
            *(uint32_t*)(sm1 + (ah - sb) + 60) = 0;   // k = 30,31
            *(uint32_t*)(sm1 + (al - sb) + 60) = 0;
        }
    }
    __syncthreads();

    // preload B fragments: [ks][n8][2], hi and lo
    int bRow = (lane & 7) + (lane >> 4) * 8;
    int bKb  = ((lane >> 3) & 1) * 16;
    uint32_t bh[2][2][2], bl[2][2][2];
#pragma unroll
    for (int ks = 0; ks < 2; ks++) {
        ldsm_x4(sb + C1_B + bRow * 80 + ks * 32 + bKb,
                bh[ks][0][0], bh[ks][0][1], bh[ks][1][0], bh[ks][1][1]);
        ldsm_x4(sb + C1_B + 1280 + bRow * 80 + ks * 32 + bKb,
                bl[ks][0][0], bl[ks][0][1], bl[ks][1][0], bl[ks][1][1]);
    }

    int aRow = (lane & 7) + ((lane >> 3) & 1) * 8;
    int aKb  = (lane >> 4) * 16;

    float acc[9][2][4];
#pragma unroll
    for (int j = 0; j < 9; j++)
#pragma unroll
        for (int n = 0; n < 2; n++)
#pragma unroll
            for (int q = 0; q < 4; q++) acc[j][n][q] = 0.0f;

#pragma unroll
    for (int j = 0; j < 9; j++) {
        int m0 = (wpid * 9 + j) * 16;
#pragma unroll
        for (int ks = 0; ks < 2; ks++) {
            uint32_t ah[4], al[4];
            ldsm_x4(sb + C1_A  + (m0 + aRow) * 80 + ks * 32 + aKb, ah[0], ah[1], ah[2], ah[3]);
            ldsm_x4(sb + C1_ALO + (m0 + aRow) * 80 + ks * 32 + aKb, al[0], al[1], al[2], al[3]);
#pragma unroll
            for (int n = 0; n < 2; n++) {
                mma_bf16(acc[j][n], ah, bh[ks][n]);
                mma_bf16(acc[j][n], ah, bl[ks][n]);
                mma_bf16(acc[j][n], al, bh[ks][n]);
            }
        }
    }
    __syncthreads();   // A reads done; OUT may overwrite

    float* o = (float*)(sm1 + C1_OUT);
#pragma unroll
    for (int j = 0; j < 9; j++) {
        int r = (wpid * 9 + j) * 16 + (lane >> 2);
#pragma unroll
        for (int n = 0; n < 2; n++) {
            int c = n * 8 + (lane & 3) * 2;
            float2 v0 = {acc[j][n][0], acc[j][n][1]};
            float2 v1 = {acc[j][n][2], acc[j][n][3]};
            *(float2*)&o[r * 18 + c] = v0;
            *(float2*)&o[(r + 8) * 18 + c] = v1;
        }
    }
    __syncthreads();

    // pool: 144 pos x 8 ch-pairs = 1152 items; relu(max4 + bias), split hi/lo
    for (int i = tid; i < 1152; i += 128) {
        int opos = i >> 3;
        int cp = (i & 7) * 2;
        int py = opos / 12, px = opos - py * 12;
        const float* o0 = &o[((2 * py) * 24 + 2 * px) * 18];
        const float* o1 = o0 + 18;
        const float* o2 = o0 + 24 * 18;
        const float* o3 = o2 + 18;
        float m0 = fmaxf(fmaxf(o0[cp], o1[cp]), fmaxf(o2[cp], o3[cp])) + __ldg(&bias[cp]);
        float m1 = fmaxf(fmaxf(o0[cp + 1], o1[cp + 1]), fmaxf(o2[cp + 1], o3[cp + 1]))
                   + __ldg(&bias[cp + 1]);
        m0 = fmaxf(m0, 0.0f);
        m1 = fmaxf(m1, 0.0f);
        __nv_bfloat16 h0 = __float2bfloat16(m0), h1 = __float2bfloat16(m1);
        int pbase = (b * 144 + opos) * CHP + cp;
        *(uint32_t*)(ph + pbase) =
            (uint32_t)__bfloat16_as_ushort(h0) | ((uint32_t)__bfloat16_as_ushort(h1) << 16);
        *(uint32_t*)(pl + pbase) =
            bf16pack(m0 - __bfloat162float(h0), m1 - __bfloat162float(h1));
    }
}

// ====== Kernel 2: conv2 via HMMA implicit conv, 3-pass split-bf16 (fp32-exact) ==
#define C2_POOLH 0
#define C2_POOLL 13824
#define C2_BHO   27648
#define C2_BLO   41472
#define C2_OUTF  0
#define C2_BIAS  55296
#define C2_SMEM  55424
__global__ void __launch_bounds__(256)
k_conv2_mma(const __nv_bfloat16* __restrict__ ph,
            const __nv_bfloat16* __restrict__ pl,
            const float* __restrict__ w2,     // [32][16][3][3]
            const float* __restrict__ bias,
            float* __restrict__ feat,
            __nv_bfloat16* __restrict__ featbf) {
    extern __shared__ __align__(16) unsigned char sm[];
    uint32_t sb = smem_u32(sm);
    int tid = threadIdx.x;
    int w8 = tid >> 5, lane = tid & 31;
    int b0 = blockIdx.x * 2;
    int img = w8 >> 2;
    int wbase = (w8 & 3) * 32;

    for (int c = tid; c < 1728; c += 256) {
        int im = c / 864; int r = c % 864; int plane = r / 432; int off = (r % 432) * 16;
        uint32_t dst = sb + (plane ? C2_POOLL : C2_POOLH) + im * 6912 + off;
        const __nv_bfloat16* src = (plane ? pl : ph) + (size_t)(b0 + im) * (144 * CHP);
        cp_async16(dst, (const char*)src + off);
    }
    CP_COMMIT();

    for (int i = tid; i < 4608; i += 256) {
        int tap = i >> 9; int oc = (i >> 4) & 31; int ch = i & 15;
        float v = w2[(oc * 16 + ch) * 9 + tap];
        __nv_bfloat16 h = __float2bfloat16(v);
        int off = ((tap * 32 + oc) * CHP + ch) * 2;
        *(__nv_bfloat16*)(sm + C2_BHO + off) = h;
        *(__nv_bfloat16*)(sm + C2_BLO + off) = __float2bfloat16(v - __bfloat162float(h));
    }
    if (tid < 32) *(float*)(sm + C2_BIAS + tid * 4) = bias[tid];
    CP_WAIT(0);
    __syncthreads();

    int posIdx[2];
#pragma unroll
    for (int mi = 0; mi < 2; mi++) {
        int pos = wbase + mi * 16 + (lane & 15);
        pos = min(pos, 99);
        posIdx[mi] = (pos / 10) * 12 + (pos % 10);
    }
    int chOff = (lane >> 4) * 16;
    uint32_t aBaseH = sb + C2_POOLH + img * 6912 + chOff;
    uint32_t aBaseL = sb + C2_POOLL + img * 6912 + chOff;
    int bRow = (lane & 7) + (lane >> 4) * 8;
    int bKb = ((lane >> 3) & 1) * 16;
    uint32_t bBaseH = sb + C2_BHO + bRow * (CHP * 2) + bKb;
    uint32_t bBaseL = sb + C2_BLO + bRow * (CHP * 2) + bKb;

    float acc[2][4][4];
#pragma unroll
    for (int i = 0; i < 2; i++)
#pragma unroll
        for (int j = 0; j < 4; j++)
#pragma unroll
            for (int q = 0; q < 4; q++) acc[i][j][q] = 0.0f;

    const int tapOff[9] = {0, 1, 2, 12, 13, 14, 24, 25, 26};
#pragma unroll
    for (int tap = 0; tap < 9; tap++) {
        int to = tapOff[tap] * (CHP * 2);
        uint32_t ah[2][4], al[2][4], bh[4][2], bl[4][2];
#pragma unroll
        for (int mi = 0; mi < 2; mi++) {
            ldsm_x4(aBaseH + posIdx[mi] * (CHP * 2) + to, ah[mi][0], ah[mi][1], ah[mi][2], ah[mi][3]);
            ldsm_x4(aBaseL + posIdx[mi] * (CHP * 2) + to, al[mi][0], al[mi][1], al[mi][2], al[mi][3]);
        }
#pragma unroll
        for (int j2 = 0; j2 < 2; j2++) {
            uint32_t off = (tap * 32 + j2 * 16) * (CHP * 2);
            ldsm_x4(bBaseH + off, bh[2 * j2][0], bh[2 * j2][1], bh[2 * j2 + 1][0], bh[2 * j2 + 1][1]);
            ldsm_x4(bBaseL + off, bl[2 * j2][0], bl[2 * j2][1], bl[2 * j2 + 1][0], bl[2 * j2 + 1][1]);
        }
#pragma unroll
        for (int mi = 0; mi < 2; mi++)
#pragma unroll
            for (int nj = 0; nj < 4; nj++) {
                mma_bf16(acc[mi][nj], ah[mi], bh[nj]);
                mma_bf16(acc[mi][nj], ah[mi], bl[nj]);
                mma_bf16(acc[mi][nj], al[mi], bh[nj]);
            }
    }

    __syncthreads();   // all smem reads done — OUTF may overwrite pool/weights

#pragma unroll
    for (int mi = 0; mi < 2; mi++) {
        int pr = wbase + mi * 16 + (lane >> 2);
#pragma unroll
        for (int nj = 0; nj < 4; nj++) {
            int c0 = nj * 8 + (lane & 3) * 2;
            float bb0 = *(float*)(sm + C2_BIAS + c0 * 4);
            float bb1 = *(float*)(sm + C2_BIAS + (c0 + 1) * 4);
            float* o = (float*)(sm + C2_OUTF) + img * 3616;
            if (pr < 100) {
                o[c0 * 113 + pr]       = fmaxf(acc[mi][nj][0] + bb0, 0.0f);
                o[(c0 + 1) * 113 + pr] = fmaxf(acc[mi][nj][1] + bb1, 0.0f);
            }
            if (pr + 8 < 100) {
                o[c0 * 113 + pr + 8]       = fmaxf(acc[mi][nj][2] + bb0, 0.0f);
                o[(c0 + 1) * 113 + pr + 8] = fmaxf(acc[mi][nj][3] + bb1, 0.0f);
            }
        }
    }
    __syncthreads();

    for (int i = tid; i < 3200; i += 256) {
        int im = i / 1600;
        int p2 = i - im * 1600;
        int oc = p2 / 50;
        int pos = (p2 - oc * 50) * 2;
        const float* o = (const float*)(sm + C2_OUTF) + im * 3616 + oc * 113 + pos;
        float v0 = o[0], v1 = o[1];
        size_t g = (size_t)(b0 + im) * DIN + oc * 100 + pos;
        float2 fv = {v0, v1};
        *(float2*)(feat + g) = fv;
        *(uint32_t*)(featbf + g) = bf16pack(v0, v1);
    }
}

// ================ Kernel 2b: W1e [5,3200,128] fp32 -> W1t [5,128,3200] bf16 =====
__global__ void k_w1_convert(const float* __restrict__ W1e,
                             __nv_bfloat16* __restrict__ W1t) {
    __shared__ float t[32][33];
    int e = blockIdx.z;
    int k0 = blockIdx.x * 32;
    int n0 = blockIdx.y * 32;
    int tx = threadIdx.x, ty = threadIdx.y;
    const float* Win = W1e + (size_t)e * DIN * DH;
    __nv_bfloat16* Wout = W1t + (size_t)e * DH * DIN;
#pragma unroll
    for (int yy = ty; yy < 32; yy += 8)
        t[yy][tx] = Win[(size_t)(k0 + yy) * DH + n0 + tx];
    __syncthreads();
#pragma unroll
    for (int yy = ty; yy < 32; yy += 8)
        Wout[(size_t)(n0 + yy) * DIN + k0 + tx] = __float2bfloat16(t[tx][yy]);
}

// ================ Kernel 2b': W2e [5,128,128] fp32 -> W2t [5][g][h] bf16 ========
__global__ void k_w2_convert(const float* __restrict__ W2e,
                             __nv_bfloat16* __restrict__ W2t) {
    __shared__ float t[32][33];
    int e = blockIdx.z;
    int h0 = blockIdx.x * 32;
    int g0 = blockIdx.y * 32;
    int tx = threadIdx.x, ty = threadIdx.y;
    const float* Win = W2e + (size_t)e * DH * DH;
    __nv_bfloat16* Wout = W2t + (size_t)e * DH * DH;
#pragma unroll
    for (int yy = ty; yy < 32; yy += 8)
        t[yy][tx] = Win[(h0 + yy) * DH + g0 + tx];
    __syncthreads();
#pragma unroll
    for (int yy = ty; yy < 32; yy += 8)
        Wout[(g0 + yy) * DH + h0 + tx] = __float2bfloat16(t[tx][yy]);
}

// ================ Kernel 2c: [Wg|Wglu] -> wgT [10][3200] fp32 ===================
__global__ void k_wgt(const float* __restrict__ Wg, const float* __restrict__ Wgl,
                      float* __restrict__ wgT) {
    int i = blockIdx.x * 256 + threadIdx.x;
    if (i >= 10 * DIN) return;
    int e = i / DIN, k = i % DIN;
    wgT[i] = (e < 5) ? Wg[k * 5 + e] : Wgl[k * 5 + (e - 5)];
}

// ================= Kernel 3: GLU router (fp32, coalesced) =======================
__global__ void k_router(const float* __restrict__ feat,
                         const float* __restrict__ wgT,
                         const float* __restrict__ bg, const float* __restrict__ bgl,
                         float* __restrict__ gw) {
    int warp = (blockIdx.x * blockDim.x + threadIdx.x) >> 5;
    int lane = threadIdx.x & 31;
    if (warp >= BATCH) return;
    const float4* f4 = (const float4*)(feat + (size_t)warp * DIN);
    float acc[10];
#pragma unroll
    for (int e = 0; e < 10; e++) acc[e] = 0.0f;
#pragma unroll 5
    for (int it = 0; it < 25; it++) {
        int k4 = it * 32 + lane;
        float4 fv = f4[k4];
#pragma unroll
        for (int e = 0; e < 10; e++) {
            float4 wv = ((const float4*)(wgT + e * DIN))[k4];
            acc[e] += fv.x * wv.x + fv.y * wv.y + fv.z * wv.z + fv.w * wv.w;
        }
    }
#pragma unroll
    for (int off = 16; off; off >>= 1)
#pragma unroll
        for (int e = 0; e < 10; e++)
            acc[e] += __shfl_down_sync(0xFFFFFFFFu, acc[e], off);

    if (lane == 0) {
        float gate[NEXP];
#pragma unroll
        for (int e = 0; e < NEXP; e++) {
            float g = acc[e] + bg[e];
            float s = 1.0f / (1.0f + expf(-(acc[5 + e] + bgl[e])));
            gate[e] = g * s;
        }
        float v0 = -1e30f, v1 = -1e30f, v2 = -1e30f;
        int i0 = 0, i1 = 0, i2 = 0;
#pragma unroll
        for (int e = 0; e < NEXP; e++) {
            float g = gate[e];
            if (g > v0)      { v2 = v1; i2 = i1; v1 = v0; i1 = i0; v0 = g; i0 = e; }
            else if (g > v1) { v2 = v1; i2 = i1; v1 = g;  i1 = e; }
            else if (g > v2) { v2 = g;  i2 = e; }
        }
        float e1 = expf(v1 - v0);
        float e2 = expf(v2 - v0);
        float inv = 1.0f / (1.0f + e1 + e2);
        float wout[NEXP];
#pragma unroll
        for (int e = 0; e < NEXP; e++) wout[e] = 0.0f;
        wout[i0] = inv; wout[i1] = e1 * inv; wout[i2] = e2 * inv;
#pragma unroll
        for (int e = 0; e < NEXP; e++) gw[warp * NEXP + e] = wout[e];
    }
}

// ===== Kernel 4: e1 = tanh(feat @ W1e + b1e) — HMMA, 3-stage cp.async pipeline ==
#define BKC   32
#define NTC   (DIN / BKC)          // 100 k-chunks
#define PITCH 80                   // bytes per 32-bf16 row
#define G1_TILE (128 * PITCH)      // 10240 per operand stage
#define G1_SMEM (6 * G1_TILE)      // 3 stages x (A + B) = 61440
__global__ void __launch_bounds__(256)
k_gemm1_mma(const __nv_bfloat16* __restrict__ A,
            const __nv_bfloat16* __restrict__ Bt,
            const float* __restrict__ b1e,
            __nv_bfloat16* __restrict__ E1bf) {     // [8192,640] bf16
    extern __shared__ __align__(128) unsigned char dsm[];
    uint32_t sA0 = smem_u32(dsm);
    uint32_t sB0 = sA0 + 3 * G1_TILE;

    int tid = threadIdx.x;
    int w = tid >> 5, lane = tid & 31;
    int wm = w & 3, wn = w >> 2;
    int mb = blockIdx.x, e = blockIdx.y;

    const __nv_bfloat16* Ab = A  + (size_t)(mb * 128) * DIN;
    const __nv_bfloat16* Bb = Bt + (size_t)e * DH * DIN;

    float acc[2][8][4];
#pragma unroll
    for (int i = 0; i < 2; i++)
#pragma unroll
        for (int j = 0; j < 8; j++)
#pragma unroll
            for (int q = 0; q < 4; q++) acc[i][j][q] = 0.0f;

    int lr = tid >> 1;
    int lc = (tid & 1) * 2;
    auto load_tile = [&](int t, int s) {
        int k0 = t * BKC;
        uint32_t aD = sA0 + s * G1_TILE + lr * PITCH + lc * 16;
        uint32_t bD = sB0 + s * G1_TILE + lr * PITCH + lc * 16;
        const __nv_bfloat16* aS = Ab + (size_t)lr * DIN + k0 + lc * 8;
        const __nv_bfloat16* bS = Bb + (size_t)lr * DIN + k0 + lc * 8;
        cp_async16(aD,      aS);
        cp_async16(aD + 16, aS + 8);
        cp_async16(bD,      bS);
        cp_async16(bD + 16, bS + 8);
    };

    load_tile(0, 0); CP_COMMIT();
    load_tile(1, 1); CP_COMMIT();

    int aRow = (lane & 7) + ((lane >> 3) & 1) * 8;
    int aKb  = (lane >> 4) * 16;
    int bRow = (lane & 7) + (lane >> 4) * 8;
    int bKb  = ((lane >> 3) & 1) * 16;

    int s = 0;                     // stage = t % 3
    for (int t = 0; t < NTC; t++) {
        CP_WAIT(1);                // tile t's group complete (t+1 may pend)
        __syncthreads();           // everyone done computing t-1 before refilling
        if (t + 2 < NTC) {
            int s2 = s + 2; if (s2 >= 3) s2 -= 3;
            load_tile(t + 2, s2);
        }
        CP_COMMIT();               // always commit (uniform group accounting)

        uint32_t aT = sA0 + s * G1_TILE;
        uint32_t bT = sB0 + s * G1_TILE;
#pragma unroll
        for (int ks = 0; ks < 2; ks++) {
            uint32_t a[2][4], b[8][2];
#pragma unroll
            for (int i = 0; i < 2; i++) {
                uint32_t addr = aT + (wm * 32 + i * 16 + aRow) * PITCH + ks * 32 + aKb;
                ldsm_x4(addr, a[i][0], a[i][1], a[i][2], a[i][3]);
            }
#pragma unroll
            for (int j2 = 0; j2 < 4; j2++) {
                uint32_t addr = bT + (wn * 64 + j2 * 16 + bRow) * PITCH + ks * 32 + bKb;
                ldsm_x4(addr, b[2 * j2][0], b[2 * j2][1], b[2 * j2 + 1][0], b[2 * j2 + 1][1]);
            }
#pragma unroll
            for (int i = 0; i < 2; i++)
#pragma unroll
                for (int j = 0; j < 8; j++)
                    mma_bf16(acc[i][j], a[i], b[j]);
        }
        if (++s == 3) s = 0;
    }

    const float* bias = b1e + e * DH;
    int qr = lane >> 2;
    int qc = (lane & 3) * 2;
#pragma unroll
    for (int i = 0; i < 2; i++) {
        int m0 = mb * 128 + wm * 32 + i * 16 + qr;
#pragma unroll
        for (int j = 0; j < 8; j++) {
            int c = wn * 64 + j * 8 + qc;
            float b0 = __ldg(&bias[c]);
            float b1 = __ldg(&bias[c + 1]);
            uint32_t p0 = bf16pack(tanhf(acc[i][j][0] + b0), tanhf(acc[i][j][1] + b1));
            uint32_t p1 = bf16pack(tanhf(acc[i][j][2] + b0), tanhf(acc[i][j][3] + b1));
            *(uint32_t*)(E1bf + (size_t)m0 * (NEXP * DH) + e * DH + c) = p0;
            *(uint32_t*)(E1bf + (size_t)(m0 + 8) * (NEXP * DH) + e * DH + c) = p1;
        }
    }
}

// ====== Kernel 5: expert-2 via HMMA bf16 + weighted combine + head + softmax ====
#define E2P   272                       // smem row pitch bytes (136 bf16)
#define E2_SA  0                        // A: 32 x 136 bf16 = 8704
#define E2_SB  8704                     // B: 128 x 136 bf16 = 34816
#define E2_MOE 43520                    // 32 x 128 f32 = 16384
#define E2_WS  59904                    // 1280 f32 = 5120
#define E2_GW  65024                    // 160 f32 = 640
#define E2_LOG 65664                    // 320 f32 = 1280
#define E2_SMEM 66944
__global__ void __launch_bounds__(256)
k_expert2_mma(const __nv_bfloat16* __restrict__ E1bf,   // [8192,640]
              const __nv_bfloat16* __restrict__ W2t,    // [5][g][h]
              const float* __restrict__ b2e,            // [5,128]
              const float* __restrict__ gw,             // [8192,5]
              const float* __restrict__ Ws,             // [128,10]
              const float* __restrict__ bs,             // [10]
              float* __restrict__ out) {                // [8192,10]
    extern __shared__ __align__(16) unsigned char dsm[];
    uint32_t sb = smem_u32(dsm);
    int tid = threadIdx.x;
    int w = tid >> 5, lane = tid & 31;
    int b0 = blockIdx.x * 32;

    float* s_ws  = (float*)(dsm + E2_WS);
    float* s_gw  = (float*)(dsm + E2_GW);
    float* s_moe = (float*)(dsm + E2_MOE);
    float* s_log = (float*)(dsm + E2_LOG);

    for (int i = tid; i < 1280; i += 256) s_ws[i] = Ws[i];
    for (int i = tid; i < 160; i += 256)  s_gw[i] = gw[b0 * NEXP + i];

    int aRow = (lane & 7) + ((lane >> 3) & 1) * 8;
    int aKb  = (lane >> 4) * 16;
    int bRow = (lane & 7) + (lane >> 4) * 8 + w * 16;
    int bKb  = ((lane >> 3) & 1) * 16;

    float moe[2][2][4];
#pragma unroll
    for (int i = 0; i < 2; i++)
#pragma unroll
        for (int j = 0; j < 2; j++)
#pragma unroll
            for (int q = 0; q < 4; q++) moe[i][j][q] = 0.0f;

    for (int e = 0; e < NEXP; e++) {
        __syncthreads();   // prior compute done before overwriting tiles
        for (int c = tid; c < 512; c += 256) {
            int r = c >> 4, ck = c & 15;
            cp_async16(sb + E2_SA + r * E2P + ck * 16,
                       E1bf + (size_t)(b0 + r) * (NEXP * DH) + e * DH + ck * 8);
        }
        for (int c = tid; c < 2048; c += 256) {
            int r = c >> 4, ck = c & 15;
            cp_async16(sb + E2_SB + r * E2P + ck * 16,
                       W2t + (size_t)e * DH * DH + r * DH + ck * 8);
        }
        CP_COMMIT(); CP_WAIT(0);
        __syncthreads();

        float acc[2][2][4];
#pragma unroll
        for (int i = 0; i < 2; i++)
#pragma unroll
            for (int j = 0; j < 2; j++)
#pragma unroll
                for (int q = 0; q < 4; q++) acc[i][j][q] = 0.0f;

#pragma unroll
        for (int k16 = 0; k16 < 8; k16++) {
            uint32_t a[2][4], b[2][2];
#pragma unroll
            for (int i = 0; i < 2; i++)
                ldsm_x4(sb + E2_SA + (i * 16 + aRow) * E2P + k16 * 32 + aKb,
                        a[i][0], a[i][1], a[i][2], a[i][3]);
            ldsm_x4(sb + E2_SB + bRow * E2P + k16 * 32 + bKb,
                    b[0][0], b[0][1], b[1][0], b[1][1]);
#pragma unroll
            for (int i = 0; i < 2; i++)
#pragma unroll
                for (int j = 0; j < 2; j++)
                    mma_bf16(acc[i][j], a[i], b[j]);
        }

#pragma unroll
        for (int i = 0; i < 2; i++)
#pragma unroll
            for (int j = 0; j < 2; j++)
#pragma unroll
                for (int q = 0; q < 4; q++) {
                    int row = i * 16 + (lane >> 2) + ((q >> 1) ? 8 : 0);
                    int g = w * 16 + j * 8 + (lane & 3) * 2 + (q & 1);
                    float pre = acc[i][j][q] + __ldg(&b2e[e * DH + g]);
                    moe[i][j][q] += s_gw[row * NEXP + e] * tanhf(pre);
                }
    }

    __syncthreads();
#pragma unroll
    for (int i = 0; i < 2; i++)
#pragma unroll
        for (int j = 0; j < 2; j++)
#pragma unroll
            for (int q = 0; q < 4; q++) {
                int row = i * 16 + (lane >> 2) + ((q >> 1) ? 8 : 0);
                int g = w * 16 + j * 8 + (lane & 3) * 2 + (q & 1);
                s_moe[row * DH + g] = moe[i][j][q];
            }
    __syncthreads();

    for (int i = tid; i < 320; i += 256) {
        int r = i / 10, c = i % 10;
        float a = __ldg(&bs[c]);
#pragma unroll 16
        for (int hh = 0; hh < 128; hh++)
            a += s_moe[r * DH + hh] * s_ws[hh * 10 + c];
        s_log[r * 10 + c] = a;
    }
    __syncthreads();
    if (tid < 32) {
        int r = tid;
        float m = -1e30f;
#pragma unroll
        for (int c = 0; c < 10; c++) m = fmaxf(m, s_log[r * 10 + c]);
        float ex[10], ssum = 0.0f;
#pragma unroll
        for (int c = 0; c < 10; c++) { ex[c] = expf(s_log[r * 10 + c] - m); ssum += ex[c]; }
        float inv = 1.0f / ssum;
        float* orow = out + (size_t)(b0 + r) * 10;
#pragma unroll
        for (int c = 0; c < 10; c++) orow[c] = ex[c] * inv;
    }
}

// =============================== launcher =======================================
extern "C" void kernel_launch(void* const* d_in, const int* in_sizes, int n_in,
                              void* d_out, int out_size) {
    const float* x       = (const float*)d_in[0];
    const float* conv1_w = (const float*)d_in[1];
    const float* conv1_b = (const float*)d_in[2];
    const float* conv2_w = (const float*)d_in[3];
    const float* conv2_b = (const float*)d_in[4];
    const float* Wg      = (const float*)d_in[5];
    const float* bg      = (const float*)d_in[6];
    const float* Wglu    = (const float*)d_in[7];
    const float* bglu    = (const float*)d_in[8];
    const float* W1e     = (const float*)d_in[9];
    const float* b1e     = (const float*)d_in[10];
    const float* W2e     = (const float*)d_in[11];
    const float* b2e     = (const float*)d_in[12];
    const float* Ws      = (const float*)d_in[13];
    const float* bs      = (const float*)d_in[14];
    float* out = (float*)d_out;

    float *feat, *wgT, *gwp;
    __nv_bfloat16 *poolh, *pooll, *featbf, *w1t, *w2t, *e1bf;
    cudaGetSymbolAddress((void**)&poolh,  g_poolt_h);
    cudaGetSymbolAddress((void**)&pooll,  g_poolt_l);
    cudaGetSymbolAddress((void**)&feat,   g_feat);
    cudaGetSymbolAddress((void**)&featbf, g_featbf);
    cudaGetSymbolAddress((void**)&w1t,    g_w1t);
    cudaGetSymbolAddress((void**)&w2t,    g_w2t);
    cudaGetSymbolAddress((void**)&wgT,    g_wgT);
    cudaGetSymbolAddress((void**)&gwp,    g_gw);
    cudaGetSymbolAddress((void**)&e1bf,   g_e1bf);

    cudaFuncSetAttribute(k_conv1_mma,   cudaFuncAttributeMaxDynamicSharedMemorySize, C1_SMEM);
    cudaFuncSetAttribute(k_conv2_mma,   cudaFuncAttributeMaxDynamicSharedMemorySize, C2_SMEM);
    cudaFuncSetAttribute(k_gemm1_mma,   cudaFuncAttributeMaxDynamicSharedMemorySize, G1_SMEM);
    cudaFuncSetAttribute(k_expert2_mma, cudaFuncAttributeMaxDynamicSharedMemorySize, E2_SMEM);

    k_wgt<<<(10 * DIN + 255) / 256, 256>>>(Wg, Wglu, wgT);
    dim3 gW(DIN / 32, DH / 32, NEXP);
    k_w1_convert<<<gW, dim3(32, 8)>>>(W1e, w1t);
    dim3 gW2(DH / 32, DH / 32, NEXP);
    k_w2_convert<<<gW2, dim3(32, 8)>>>(W2e, w2t);
    k_conv1_mma<<<BATCH, 128, C1_SMEM>>>(x, conv1_w, conv1_b, poolh, pooll);
    k_conv2_mma<<<BATCH / 2, 256, C2_SMEM>>>(poolh, pooll, conv2_w, conv2_b, feat, featbf);
    k_router<<<BATCH / 8, 256>>>(feat, wgT, bg, bglu, gwp);
    dim3 g4(BATCH / 128, NEXP);
    k_gemm1_mma<<<g4, 256, G1_SMEM>>>(featbf, w1t, b1e, e1bf);
    k_expert2_mma<<<BATCH / 32, 256, E2_SMEM>>>(e1bf, w2t, b2e, gwp, Ws, bs, out);
}

// round 14
// speedup vs baseline: 1.1973x; 1.1973x over previous
#include <cuda_runtime.h>
#include <cuda_bf16.h>
#include <math.h>
#include <stdint.h>

#define BATCH 8192
#define DIN   3200
#define DH    128
#define NEXP  5
#define CHP   24      // channel pitch for pool tiles (48B rows: 16B-aligned, conflict-free)

// ---------------- scratch (static device memory; no allocation) ----------------
__device__ __nv_bfloat16 g_poolt_h[BATCH * 144 * CHP]; // conv1 out hi [B][pos][24]
__device__ __nv_bfloat16 g_poolt_l[BATCH * 144 * CHP]; // conv1 out lo
__device__ float g_feat[BATCH * DIN];                  // conv2 output fp32 (router)
__device__ __nv_bfloat16 g_featbf[BATCH * DIN];        // conv2 output bf16 (gemm1)
__device__ __nv_bfloat16 g_w1t[NEXP * DH * DIN];       // W1e transposed bf16 [5][128][3200]
__device__ __nv_bfloat16 g_w2t[NEXP * DH * DH];        // W2e transposed bf16 [5][g][h]
__device__ float g_wgT[10 * DIN];                      // [Wg|Wglu]^T fp32
__device__ float g_gw  [BATCH * NEXP];                 // routing weights [B,5]
__device__ __nv_bfloat16 g_e1bf[BATCH * NEXP * DH];    // expert layer-1 bf16 [B,640]

// =========================== PTX helpers (baseline ISA only) ====================
__device__ __forceinline__ uint32_t smem_u32(const void* p) {
    uint32_t a;
    asm("{ .reg .u64 t; cvta.to.shared.u64 t, %1; cvt.u32.u64 %0, t; }" : "=r"(a) : "l"(p));
    return a;
}
__device__ __forceinline__ void cp_async16(uint32_t dst, const void* src) {
    asm volatile("cp.async.cg.shared.global [%0], [%1], 16;" :: "r"(dst), "l"(src) : "memory");
}
#define CP_COMMIT() asm volatile("cp.async.commit_group;" ::: "memory")
#define CP_WAIT(n)  asm volatile("cp.async.wait_group %0;" :: "n"(n) : "memory")

__device__ __forceinline__ void ldsm_x4(uint32_t addr, uint32_t& r0, uint32_t& r1,
                                        uint32_t& r2, uint32_t& r3) {
    asm volatile("ldmatrix.sync.aligned.m8n8.x4.shared.b16 {%0,%1,%2,%3}, [%4];"
                 : "=r"(r0), "=r"(r1), "=r"(r2), "=r"(r3) : "r"(addr));
}
__device__ __forceinline__ void mma_bf16(float* d, const uint32_t* a, const uint32_t* b) {
    asm volatile("mma.sync.aligned.m16n8k16.row.col.f32.bf16.bf16.f32 "
                 "{%0,%1,%2,%3}, {%4,%5,%6,%7}, {%8,%9}, {%0,%1,%2,%3};"
                 : "+f"(d[0]), "+f"(d[1]), "+f"(d[2]), "+f"(d[3])
                 : "r"(a[0]), "r"(a[1]), "r"(a[2]), "r"(a[3]), "r"(b[0]), "r"(b[1]));
}
__device__ __forceinline__ uint32_t bf16pack(float a, float b) {
    return (uint32_t)__bfloat16_as_ushort(__float2bfloat16(a)) |
           ((uint32_t)__bfloat16_as_ushort(__float2bfloat16(b)) << 16);
}

// ====== Kernel 1: conv1 (5x5) + ReLU + maxpool — tiled HMMA im2col (v2) =========
// 1 image/CTA, 256 threads. 12 chunks of 48 positions (2 conv-rows -> 1 pooled
// row). A chunk 48x[K=32] hi/lo (3-pass split-bf16 = fp32-exact), pooled on the
// fly. smem 16.9KB -> 4 CTA/SM, full warp occupancy.
#define C1_B    3200        // B hi 16x80=1280, lo at 4480
#define C1_AH   5760        // A hi 48x80 = 3840
#define C1_AL   9600        // A lo 48x80 = 3840
#define C1_OUT  13440       // f32 [48][18] = 3456 -> total 16896
__global__ void __launch_bounds__(256)
k_conv1_mma(const float* __restrict__ x,
            const float* __restrict__ w,      // [16][1][5][5]
            const float* __restrict__ bias,   // [16]
            __nv_bfloat16* __restrict__ ph,
            __nv_bfloat16* __restrict__ pl) {
    __shared__ __align__(16) unsigned char sm1[16896];
    uint32_t sb = smem_u32(sm1);
    float* s_img = (float*)sm1;
    float* o = (float*)(sm1 + C1_OUT);
    int tid = threadIdx.x;
    int wpid = tid >> 5, lane = tid & 31;
    int b = blockIdx.x;

    for (int i = tid; i < 784; i += 256) s_img[i] = x[(size_t)b * 784 + i];

    // B fill: [ch][c=ky*6+kx], pads zero, hi+lo planes
    for (int i = tid; i < 640; i += 256) {
        int ch = i / 40, c = i % 40;
        float v = 0.0f;
        int ky = c / 6, kx = c - ky * 6;
        if (c < 30 && kx < 5) v = w[ch * 25 + ky * 5 + kx];
        __nv_bfloat16 h = __float2bfloat16(v);
        *(__nv_bfloat16*)(sm1 + C1_B + ch * 80 + c * 2) = h;
        *(__nv_bfloat16*)(sm1 + C1_B + 1280 + ch * 80 + c * 2) =
            __float2bfloat16(v - __bfloat162float(h));
    }
    __syncthreads();

    // preload B fragments [ks][n8][2]
    int bRow = (lane & 7) + (lane >> 4) * 8;
    int bKb  = ((lane >> 3) & 1) * 16;
    uint32_t bh[2][2][2], bl[2][2][2];
#pragma unroll
    for (int ks = 0; ks < 2; ks++) {
        ldsm_x4(sb + C1_B + bRow * 80 + ks * 32 + bKb,
                bh[ks][0][0], bh[ks][0][1], bh[ks][1][0], bh[ks][1][1]);
        ldsm_x4(sb + C1_B + 1280 + bRow * 80 + ks * 32 + bKb,
                bl[ks][0][0], bl[ks][0][1], bl[ks][1][0], bl[ks][1][1]);
    }

    int aRow = (lane & 7) + ((lane >> 3) & 1) * 8;
    int aKb  = (lane >> 4) * 16;
    int qr = lane >> 2, qc = (lane & 3) * 2;

    for (int c = 0; c < 12; c++) {
        // im2col: 240 tasks = 48 positions x 5 ky-rows, one per thread
        if (tid < 240) {
            int p2 = tid / 5, ky = tid - (tid / 5) * 5;
            int p = c * 48 + p2;
            int oy = p / 24, ox = p - (p / 24) * 24;
            const float* src = &s_img[(oy + ky) * 28 + ox];
            float v0 = src[0], v1 = src[1], v2 = src[2], v3 = src[3], v4 = src[4];
            __nv_bfloat16 h0 = __float2bfloat16(v0), h1 = __float2bfloat16(v1),
                          h2 = __float2bfloat16(v2), h3 = __float2bfloat16(v3),
                          h4 = __float2bfloat16(v4);
            uint32_t hp0 = (uint32_t)__bfloat16_as_ushort(h0) |
                           ((uint32_t)__bfloat16_as_ushort(h1) << 16);
            uint32_t hp1 = (uint32_t)__bfloat16_as_ushort(h2) |
                           ((uint32_t)__bfloat16_as_ushort(h3) << 16);
            uint32_t hp2 = (uint32_t)__bfloat16_as_ushort(h4);
            uint32_t lp0 = bf16pack(v0 - __bfloat162float(h0), v1 - __bfloat162float(h1));
            uint32_t lp1 = bf16pack(v2 - __bfloat162float(h2), v3 - __bfloat162float(h3));
            uint32_t lp2 = (uint32_t)__bfloat16_as_ushort(
                               __float2bfloat16(v4 - __bfloat162float(h4)));
            uint32_t offH = C1_AH + p2 * 80 + ky * 12;
            uint32_t offL = C1_AL + p2 * 80 + ky * 12;
            *(uint32_t*)(sm1 + offH)     = hp0;
            *(uint32_t*)(sm1 + offH + 4) = hp1;
            *(uint32_t*)(sm1 + offH + 8) = hp2;
            *(uint32_t*)(sm1 + offL)     = lp0;
            *(uint32_t*)(sm1 + offL + 4) = lp1;
            *(uint32_t*)(sm1 + offL + 8) = lp2;
            if (ky == 0) {                       // zero k=30,31
                *(uint32_t*)(sm1 + C1_AH + p2 * 80 + 60) = 0;
                *(uint32_t*)(sm1 + C1_AL + p2 * 80 + 60) = 0;
            }
        }
        __syncthreads();

        // MMA: warps 0-2 own m16 tiles of the 48-row chunk
        if (wpid < 3) {
            int m0 = wpid * 16;
            float acc[2][4];
#pragma unroll
            for (int n = 0; n < 2; n++)
#pragma unroll
                for (int q = 0; q < 4; q++) acc[n][q] = 0.0f;
#pragma unroll
            for (int ks = 0; ks < 2; ks++) {
                uint32_t ah[4], al[4];
                ldsm_x4(sb + C1_AH + (m0 + aRow) * 80 + ks * 32 + aKb,
                        ah[0], ah[1], ah[2], ah[3]);
                ldsm_x4(sb + C1_AL + (m0 + aRow) * 80 + ks * 32 + aKb,
                        al[0], al[1], al[2], al[3]);
#pragma unroll
                for (int n = 0; n < 2; n++) {
                    mma_bf16(acc[n], ah, bh[ks][n]);
                    mma_bf16(acc[n], ah, bl[ks][n]);
                    mma_bf16(acc[n], al, bh[ks][n]);
                }
            }
            // stage into OUT[48][18]
#pragma unroll
            for (int n = 0; n < 2; n++) {
                int cc = n * 8 + qc;
                float2 v0 = {acc[n][0], acc[n][1]};
                float2 v1 = {acc[n][2], acc[n][3]};
                *(float2*)&o[(m0 + qr) * 18 + cc] = v0;
                *(float2*)&o[(m0 + 8 + qr) * 18 + cc] = v1;
            }
        }
        __syncthreads();

        // pool: 12 px x 8 ch-pairs = 96 items; chunk c -> pooled row py=c
        if (tid < 96) {
            int px = tid >> 3, cp = (tid & 7) * 2;
            const float* o0 = &o[(2 * px) * 18];
            const float* o1 = o0 + 18;
            const float* o2 = &o[(24 + 2 * px) * 18];
            const float* o3 = o2 + 18;
            float m0v = fmaxf(fmaxf(o0[cp], o1[cp]), fmaxf(o2[cp], o3[cp]))
                        + __ldg(&bias[cp]);
            float m1v = fmaxf(fmaxf(o0[cp + 1], o1[cp + 1]), fmaxf(o2[cp + 1], o3[cp + 1]))
                        + __ldg(&bias[cp + 1]);
            m0v = fmaxf(m0v, 0.0f);
            m1v = fmaxf(m1v, 0.0f);
            __nv_bfloat16 h0 = __float2bfloat16(m0v), h1 = __float2bfloat16(m1v);
            int pbase = (b * 144 + c * 12 + px) * CHP + cp;
            *(uint32_t*)(ph + pbase) =
                (uint32_t)__bfloat16_as_ushort(h0) | ((uint32_t)__bfloat16_as_ushort(h1) << 16);
            *(uint32_t*)(pl + pbase) =
                bf16pack(m0v - __bfloat162float(h0), m1v - __bfloat162float(h1));
        }
        __syncthreads();
    }
}

// ====== Kernel 2: conv2 via HMMA implicit conv, 3-pass split-bf16 (fp32-exact) ==
#define C2_POOLH 0
#define C2_POOLL 13824
#define C2_BHO   27648
#define C2_BLO   41472
#define C2_OUTF  0
#define C2_BIAS  55296
#define C2_SMEM  55424
__global__ void __launch_bounds__(256)
k_conv2_mma(const __nv_bfloat16* __restrict__ ph,
            const __nv_bfloat16* __restrict__ pl,
            const float* __restrict__ w2,     // [32][16][3][3]
            const float* __restrict__ bias,
            float* __restrict__ feat,
            __nv_bfloat16* __restrict__ featbf) {
    extern __shared__ __align__(16) unsigned char sm[];
    uint32_t sb = smem_u32(sm);
    int tid = threadIdx.x;
    int w8 = tid >> 5, lane = tid & 31;
    int b0 = blockIdx.x * 2;
    int img = w8 >> 2;
    int wbase = (w8 & 3) * 32;

    for (int c = tid; c < 1728; c += 256) {
        int im = c / 864; int r = c % 864; int plane = r / 432; int off = (r % 432) * 16;
        uint32_t dst = sb + (plane ? C2_POOLL : C2_POOLH) + im * 6912 + off;
        const __nv_bfloat16* src = (plane ? pl : ph) + (size_t)(b0 + im) * (144 * CHP);
        cp_async16(dst, (const char*)src + off);
    }
    CP_COMMIT();

    for (int i = tid; i < 4608; i += 256) {
        int tap = i >> 9; int oc = (i >> 4) & 31; int ch = i & 15;
        float v = w2[(oc * 16 + ch) * 9 + tap];
        __nv_bfloat16 h = __float2bfloat16(v);
        int off = ((tap * 32 + oc) * CHP + ch) * 2;
        *(__nv_bfloat16*)(sm + C2_BHO + off) = h;
        *(__nv_bfloat16*)(sm + C2_BLO + off) = __float2bfloat16(v - __bfloat162float(h));
    }
    if (tid < 32) *(float*)(sm + C2_BIAS + tid * 4) = bias[tid];
    CP_WAIT(0);
    __syncthreads();

    int posIdx[2];
#pragma unroll
    for (int mi = 0; mi < 2; mi++) {
        int pos = wbase + mi * 16 + (lane & 15);
        pos = min(pos, 99);
        posIdx[mi] = (pos / 10) * 12 + (pos % 10);
    }
    int chOff = (lane >> 4) * 16;
    uint32_t aBaseH = sb + C2_POOLH + img * 6912 + chOff;
    uint32_t aBaseL = sb + C2_POOLL + img * 6912 + chOff;
    int bRow = (lane & 7) + (lane >> 4) * 8;
    int bKb = ((lane >> 3) & 1) * 16;
    uint32_t bBaseH = sb + C2_BHO + bRow * (CHP * 2) + bKb;
    uint32_t bBaseL = sb + C2_BLO + bRow * (CHP * 2) + bKb;

    float acc[2][4][4];
#pragma unroll
    for (int i = 0; i < 2; i++)
#pragma unroll
        for (int j = 0; j < 4; j++)
#pragma unroll
            for (int q = 0; q < 4; q++) acc[i][j][q] = 0.0f;

    const int tapOff[9] = {0, 1, 2, 12, 13, 14, 24, 25, 26};
#pragma unroll
    for (int tap = 0; tap < 9; tap++) {
        int to = tapOff[tap] * (CHP * 2);
        uint32_t ah[2][4], al[2][4], bh[4][2], bl[4][2];
#pragma unroll
        for (int mi = 0; mi < 2; mi++) {
            ldsm_x4(aBaseH + posIdx[mi] * (CHP * 2) + to, ah[mi][0], ah[mi][1], ah[mi][2], ah[mi][3]);
            ldsm_x4(aBaseL + posIdx[mi] * (CHP * 2) + to, al[mi][0], al[mi][1], al[mi][2], al[mi][3]);
        }
#pragma unroll
        for (int j2 = 0; j2 < 2; j2++) {
            uint32_t off = (tap * 32 + j2 * 16) * (CHP * 2);
            ldsm_x4(bBaseH + off, bh[2 * j2][0], bh[2 * j2][1], bh[2 * j2 + 1][0], bh[2 * j2 + 1][1]);
            ldsm_x4(bBaseL + off, bl[2 * j2][0], bl[2 * j2][1], bl[2 * j2 + 1][0], bl[2 * j2 + 1][1]);
        }
#pragma unroll
        for (int mi = 0; mi < 2; mi++)
#pragma unroll
            for (int nj = 0; nj < 4; nj++) {
                mma_bf16(acc[mi][nj], ah[mi], bh[nj]);
                mma_bf16(acc[mi][nj], ah[mi], bl[nj]);
                mma_bf16(acc[mi][nj], al[mi], bh[nj]);
            }
    }

    __syncthreads();   // all smem reads done — OUTF may overwrite pool/weights

#pragma unroll
    for (int mi = 0; mi < 2; mi++) {
        int pr = wbase + mi * 16 + (lane >> 2);
#pragma unroll
        for (int nj = 0; nj < 4; nj++) {
            int c0 = nj * 8 + (lane & 3) * 2;
            float bb0 = *(float*)(sm + C2_BIAS + c0 * 4);
            float bb1 = *(float*)(sm + C2_BIAS + (c0 + 1) * 4);
            float* o = (float*)(sm + C2_OUTF) + img * 3616;
            if (pr < 100) {
                o[c0 * 113 + pr]       = fmaxf(acc[mi][nj][0] + bb0, 0.0f);
                o[(c0 + 1) * 113 + pr] = fmaxf(acc[mi][nj][1] + bb1, 0.0f);
            }
            if (pr + 8 < 100) {
                o[c0 * 113 + pr + 8]       = fmaxf(acc[mi][nj][2] + bb0, 0.0f);
                o[(c0 + 1) * 113 + pr + 8] = fmaxf(acc[mi][nj][3] + bb1, 0.0f);
            }
        }
    }
    __syncthreads();

    for (int i = tid; i < 3200; i += 256) {
        int im = i / 1600;
        int p2 = i - im * 1600;
        int oc = p2 / 50;
        int pos = (p2 - oc * 50) * 2;
        const float* o = (const float*)(sm + C2_OUTF) + im * 3616 + oc * 113 + pos;
        float v0 = o[0], v1 = o[1];
        size_t g = (size_t)(b0 + im) * DIN + oc * 100 + pos;
        float2 fv = {v0, v1};
        *(float2*)(feat + g) = fv;
        *(uint32_t*)(featbf + g) = bf16pack(v0, v1);
    }
}

// ================ Kernel 2b: W1e [5,3200,128] fp32 -> W1t [5,128,3200] bf16 =====
__global__ void k_w1_convert(const float* __restrict__ W1e,
                             __nv_bfloat16* __restrict__ W1t) {
    __shared__ float t[32][33];
    int e = blockIdx.z;
    int k0 = blockIdx.x * 32;
    int n0 = blockIdx.y * 32;
    int tx = threadIdx.x, ty = threadIdx.y;
    const float* Win = W1e + (size_t)e * DIN * DH;
    __nv_bfloat16* Wout = W1t + (size_t)e * DH * DIN;
#pragma unroll
    for (int yy = ty; yy < 32; yy += 8)
        t[yy][tx] = Win[(size_t)(k0 + yy) * DH + n0 + tx];
    __syncthreads();
#pragma unroll
    for (int yy = ty; yy < 32; yy += 8)
        Wout[(size_t)(n0 + yy) * DIN + k0 + tx] = __float2bfloat16(t[tx][yy]);
}

// ================ Kernel 2b': W2e [5,128,128] fp32 -> W2t [5][g][h] bf16 ========
__global__ void k_w2_convert(const float* __restrict__ W2e,
                             __nv_bfloat16* __restrict__ W2t) {
    __shared__ float t[32][33];
    int e = blockIdx.z;
    int h0 = blockIdx.x * 32;
    int g0 = blockIdx.y * 32;
    int tx = threadIdx.x, ty = threadIdx.y;
    const float* Win = W2e + (size_t)e * DH * DH;
    __nv_bfloat16* Wout = W2t + (size_t)e * DH * DH;
#pragma unroll
    for (int yy = ty; yy < 32; yy += 8)
        t[yy][tx] = Win[(h0 + yy) * DH + g0 + tx];
    __syncthreads();
#pragma unroll
    for (int yy = ty; yy < 32; yy += 8)
        Wout[(g0 + yy) * DH + h0 + tx] = __float2bfloat16(t[tx][yy]);
}

// ================ Kernel 2c: [Wg|Wglu] -> wgT [10][3200] fp32 ===================
__global__ void k_wgt(const float* __restrict__ Wg, const float* __restrict__ Wgl,
                      float* __restrict__ wgT) {
    int i = blockIdx.x * 256 + threadIdx.x;
    if (i >= 10 * DIN) return;
    int e = i / DIN, k = i % DIN;
    wgT[i] = (e < 5) ? Wg[k * 5 + e] : Wgl[k * 5 + (e - 5)];
}

// ================= Kernel 3: GLU router (fp32, coalesced) =======================
__global__ void k_router(const float* __restrict__ feat,
                         const float* __restrict__ wgT,
                         const float* __restrict__ bg, const float* __restrict__ bgl,
                         float* __restrict__ gw) {
    int warp = (blockIdx.x * blockDim.x + threadIdx.x) >> 5;
    int lane = threadIdx.x & 31;
    if (warp >= BATCH) return;
    const float4* f4 = (const float4*)(feat + (size_t)warp * DIN);
    float acc[10];
#pragma unroll
    for (int e = 0; e < 10; e++) acc[e] = 0.0f;
#pragma unroll 5
    for (int it = 0; it < 25; it++) {
        int k4 = it * 32 + lane;
        float4 fv = f4[k4];
#pragma unroll
        for (int e = 0; e < 10; e++) {
            float4 wv = ((const float4*)(wgT + e * DIN))[k4];
            acc[e] += fv.x * wv.x + fv.y * wv.y + fv.z * wv.z + fv.w * wv.w;
        }
    }
#pragma unroll
    for (int off = 16; off; off >>= 1)
#pragma unroll
        for (int e = 0; e < 10; e++)
            acc[e] += __shfl_down_sync(0xFFFFFFFFu, acc[e], off);

    if (lane == 0) {
        float gate[NEXP];
#pragma unroll
        for (int e = 0; e < NEXP; e++) {
            float g = acc[e] + bg[e];
            float s = 1.0f / (1.0f + expf(-(acc[5 + e] + bgl[e])));
            gate[e] = g * s;
        }
        float v0 = -1e30f, v1 = -1e30f, v2 = -1e30f;
        int i0 = 0, i1 = 0, i2 = 0;
#pragma unroll
        for (int e = 0; e < NEXP; e++) {
            float g = gate[e];
            if (g > v0)      { v2 = v1; i2 = i1; v1 = v0; i1 = i0; v0 = g; i0 = e; }
            else if (g > v1) { v2 = v1; i2 = i1; v1 = g;  i1 = e; }
            else if (g > v2) { v2 = g;  i2 = e; }
        }
        float e1 = expf(v1 - v0);
        float e2 = expf(v2 - v0);
        float inv = 1.0f / (1.0f + e1 + e2);
        float wout[NEXP];
#pragma unroll
        for (int e = 0; e < NEXP; e++) wout[e] = 0.0f;
        wout[i0] = inv; wout[i1] = e1 * inv; wout[i2] = e2 * inv;
#pragma unroll
        for (int e = 0; e < NEXP; e++) gw[warp * NEXP + e] = wout[e];
    }
}

// ===== Kernel 4: e1 = tanh(feat @ W1e + b1e) — HMMA, 3-stage cp.async pipeline ==
#define BKC   32
#define NTC   (DIN / BKC)          // 100 k-chunks
#define PITCH 80                   // bytes per 32-bf16 row
#define G1_TILE (128 * PITCH)      // 10240 per operand stage
#define G1_SMEM (6 * G1_TILE)      // 3 stages x (A + B) = 61440
__global__ void __launch_bounds__(256)
k_gemm1_mma(const __nv_bfloat16* __restrict__ A,
            const __nv_bfloat16* __restrict__ Bt,
            const float* __restrict__ b1e,
            __nv_bfloat16* __restrict__ E1bf) {     // [8192,640] bf16
    extern __shared__ __align__(128) unsigned char dsm[];
    uint32_t sA0 = smem_u32(dsm);
    uint32_t sB0 = sA0 + 3 * G1_TILE;

    int tid = threadIdx.x;
    int w = tid >> 5, lane = tid & 31;
    int wm = w & 3, wn = w >> 2;
    int mb = blockIdx.x, e = blockIdx.y;

    const __nv_bfloat16* Ab = A  + (size_t)(mb * 128) * DIN;
    const __nv_bfloat16* Bb = Bt + (size_t)e * DH * DIN;

    float acc[2][8][4];
#pragma unroll
    for (int i = 0; i < 2; i++)
#pragma unroll
        for (int j = 0; j < 8; j++)
#pragma unroll
            for (int q = 0; q < 4; q++) acc[i][j][q] = 0.0f;

    int lr = tid >> 1;
    int lc = (tid & 1) * 2;
    auto load_tile = [&](int t, int s) {
        int k0 = t * BKC;
        uint32_t aD = sA0 + s * G1_TILE + lr * PITCH + lc * 16;
        uint32_t bD = sB0 + s * G1_TILE + lr * PITCH + lc * 16;
        const __nv_bfloat16* aS = Ab + (size_t)lr * DIN + k0 + lc * 8;
        const __nv_bfloat16* bS = Bb + (size_t)lr * DIN + k0 + lc * 8;
        cp_async16(aD,      aS);
        cp_async16(aD + 16, aS + 8);
        cp_async16(bD,      bS);
        cp_async16(bD + 16, bS + 8);
    };

    load_tile(0, 0); CP_COMMIT();
    load_tile(1, 1); CP_COMMIT();

    int aRow = (lane & 7) + ((lane >> 3) & 1) * 8;
    int aKb  = (lane >> 4) * 16;
    int bRow = (lane & 7) + (lane >> 4) * 8;
    int bKb  = ((lane >> 3) & 1) * 16;

    int s = 0;                     // stage = t % 3
    for (int t = 0; t < NTC; t++) {
        CP_WAIT(1);                // tile t's group complete (t+1 may pend)
        __syncthreads();           // everyone done computing t-1 before refilling
        if (t + 2 < NTC) {
            int s2 = s + 2; if (s2 >= 3) s2 -= 3;
            load_tile(t + 2, s2);
        }
        CP_COMMIT();               // always commit (uniform group accounting)

        uint32_t aT = sA0 + s * G1_TILE;
        uint32_t bT = sB0 + s * G1_TILE;
#pragma unroll
        for (int ks = 0; ks < 2; ks++) {
            uint32_t a[2][4], b[8][2];
#pragma unroll
            for (int i = 0; i < 2; i++) {
                uint32_t addr = aT + (wm * 32 + i * 16 + aRow) * PITCH + ks * 32 + aKb;
                ldsm_x4(addr, a[i][0], a[i][1], a[i][2], a[i][3]);
            }
#pragma unroll
            for (int j2 = 0; j2 < 4; j2++) {
                uint32_t addr = bT + (wn * 64 + j2 * 16 + bRow) * PITCH + ks * 32 + bKb;
                ldsm_x4(addr, b[2 * j2][0], b[2 * j2][1], b[2 * j2 + 1][0], b[2 * j2 + 1][1]);
            }
#pragma unroll
            for (int i = 0; i < 2; i++)
#pragma unroll
                for (int j = 0; j < 8; j++)
                    mma_bf16(acc[i][j], a[i], b[j]);
        }
        if (++s == 3) s = 0;
    }

    const float* bias = b1e + e * DH;
    int qr = lane >> 2;
    int qc = (lane & 3) * 2;
#pragma unroll
    for (int i = 0; i < 2; i++) {
        int m0 = mb * 128 + wm * 32 + i * 16 + qr;
#pragma unroll
        for (int j = 0; j < 8; j++) {
            int c = wn * 64 + j * 8 + qc;
            float b0 = __ldg(&bias[c]);
            float b1 = __ldg(&bias[c + 1]);
            uint32_t p0 = bf16pack(tanhf(acc[i][j][0] + b0), tanhf(acc[i][j][1] + b1));
            uint32_t p1 = bf16pack(tanhf(acc[i][j][2] + b0), tanhf(acc[i][j][3] + b1));
            *(uint32_t*)(E1bf + (size_t)m0 * (NEXP * DH) + e * DH + c) = p0;
            *(uint32_t*)(E1bf + (size_t)(m0 + 8) * (NEXP * DH) + e * DH + c) = p1;
        }
    }
}

// ====== Kernel 5: expert-2 via HMMA bf16 + weighted combine + head + softmax ====
#define E2P   272                       // smem row pitch bytes (136 bf16)
#define E2_SA  0                        // A: 32 x 136 bf16 = 8704
#define E2_SB  8704                     // B: 128 x 136 bf16 = 34816
#define E2_MOE 43520                    // 32 x 128 f32 = 16384
#define E2_WS  59904                    // 1280 f32 = 5120
#define E2_GW  65024                    // 160 f32 = 640
#define E2_LOG 65664                    // 320 f32 = 1280
#define E2_SMEM 66944
__global__ void __launch_bounds__(256)
k_expert2_mma(const __nv_bfloat16* __restrict__ E1bf,   // [8192,640]
              const __nv_bfloat16* __restrict__ W2t,    // [5][g][h]
              const float* __restrict__ b2e,            // [5,128]
              const float* __restrict__ gw,             // [8192,5]
              const float* __restrict__ Ws,             // [128,10]
              const float* __restrict__ bs,             // [10]
              float* __restrict__ out) {                // [8192,10]
    extern __shared__ __align__(16) unsigned char dsm[];
    uint32_t sb = smem_u32(dsm);
    int tid = threadIdx.x;
    int w = tid >> 5, lane = tid & 31;
    int b0 = blockIdx.x * 32;

    float* s_ws  = (float*)(dsm + E2_WS);
    float* s_gw  = (float*)(dsm + E2_GW);
    float* s_moe = (float*)(dsm + E2_MOE);
    float* s_log = (float*)(dsm + E2_LOG);

    for (int i = tid; i < 1280; i += 256) s_ws[i] = Ws[i];
    for (int i = tid; i < 160; i += 256)  s_gw[i] = gw[b0 * NEXP + i];

    int aRow = (lane & 7) + ((lane >> 3) & 1) * 8;
    int aKb  = (lane >> 4) * 16;
    int bRow = (lane & 7) + (lane >> 4) * 8 + w * 16;
    int bKb  = ((lane >> 3) & 1) * 16;

    float moe[2][2][4];
#pragma unroll
    for (int i = 0; i < 2; i++)
#pragma unroll
        for (int j = 0; j < 2; j++)
#pragma unroll
            for (int q = 0; q < 4; q++) moe[i][j][q] = 0.0f;

    for (int e = 0; e < NEXP; e++) {
        __syncthreads();   // prior compute done before overwriting tiles
        for (int c = tid; c < 512; c += 256) {
            int r = c >> 4, ck = c & 15;
            cp_async16(sb + E2_SA + r * E2P + ck * 16,
                       E1bf + (size_t)(b0 + r) * (NEXP * DH) + e * DH + ck * 8);
        }
        for (int c = tid; c < 2048; c += 256) {
            int r = c >> 4, ck = c & 15;
            cp_async16(sb + E2_SB + r * E2P + ck * 16,
                       W2t + (size_t)e * DH * DH + r * DH + ck * 8);
        }
        CP_COMMIT(); CP_WAIT(0);
        __syncthreads();

        float acc[2][2][4];
#pragma unroll
        for (int i = 0; i < 2; i++)
#pragma unroll
            for (int j = 0; j < 2; j++)
#pragma unroll
                for (int q = 0; q < 4; q++) acc[i][j][q] = 0.0f;

#pragma unroll
        for (int k16 = 0; k16 < 8; k16++) {
            uint32_t a[2][4], b[2][2];
#pragma unroll
            for (int i = 0; i < 2; i++)
                ldsm_x4(sb + E2_SA + (i * 16 + aRow) * E2P + k16 * 32 + aKb,
                        a[i][0], a[i][1], a[i][2], a[i][3]);
            ldsm_x4(sb + E2_SB + bRow * E2P + k16 * 32 + bKb,
                    b[0][0], b[0][1], b[1][0], b[1][1]);
#pragma unroll
            for (int i = 0; i < 2; i++)
#pragma unroll
                for (int j = 0; j < 2; j++)
                    mma_bf16(acc[i][j], a[i], b[j]);
        }

#pragma unroll
        for (int i = 0; i < 2; i++)
#pragma unroll
            for (int j = 0; j < 2; j++)
#pragma unroll
                for (int q = 0; q < 4; q++) {
                    int row = i * 16 + (lane >> 2) + ((q >> 1) ? 8 : 0);
                    int g = w * 16 + j * 8 + (lane & 3) * 2 + (q & 1);
                    float pre = acc[i][j][q] + __ldg(&b2e[e * DH + g]);
                    moe[i][j][q] += s_gw[row * NEXP + e] * tanhf(pre);
                }
    }

    __syncthreads();
#pragma unroll
    for (int i = 0; i < 2; i++)
#pragma unroll
        for (int j = 0; j < 2; j++)
#pragma unroll
            for (int q = 0; q < 4; q++) {
                int row = i * 16 + (lane >> 2) + ((q >> 1) ? 8 : 0);
                int g = w * 16 + j * 8 + (lane & 3) * 2 + (q & 1);
                s_moe[row * DH + g] = moe[i][j][q];
            }
    __syncthreads();

    for (int i = tid; i < 320; i += 256) {
        int r = i / 10, c = i % 10;
        float a = __ldg(&bs[c]);
#pragma unroll 16
        for (int hh = 0; hh < 128; hh++)
            a += s_moe[r * DH + hh] * s_ws[hh * 10 + c];
        s_log[r * 10 + c] = a;
    }
    __syncthreads();
    if (tid < 32) {
        int r = tid;
        float m = -1e30f;
#pragma unroll
        for (int c = 0; c < 10; c++) m = fmaxf(m, s_log[r * 10 + c]);
        float ex[10], ssum = 0.0f;
#pragma unroll
        for (int c = 0; c < 10; c++) { ex[c] = expf(s_log[r * 10 + c] - m); ssum += ex[c]; }
        float inv = 1.0f / ssum;
        float* orow = out + (size_t)(b0 + r) * 10;
#pragma unroll
        for (int c = 0; c < 10; c++) orow[c] = ex[c] * inv;
    }
}

// =============================== launcher =======================================
extern "C" void kernel_launch(void* const* d_in, const int* in_sizes, int n_in,
                              void* d_out, int out_size) {
    const float* x       = (const float*)d_in[0];
    const float* conv1_w = (const float*)d_in[1];
    const float* conv1_b = (const float*)d_in[2];
    const float* conv2_w = (const float*)d_in[3];
    const float* conv2_b = (const float*)d_in[4];
    const float* Wg      = (const float*)d_in[5];
    const float* bg      = (const float*)d_in[6];
    const float* Wglu    = (const float*)d_in[7];
    const float* bglu    = (const float*)d_in[8];
    const float* W1e     = (const float*)d_in[9];
    const float* b1e     = (const float*)d_in[10];
    const float* W2e     = (const float*)d_in[11];
    const float* b2e     = (const float*)d_in[12];
    const float* Ws      = (const float*)d_in[13];
    const float* bs      = (const float*)d_in[14];
    float* out = (float*)d_out;

    float *feat, *wgT, *gwp;
    __nv_bfloat16 *poolh, *pooll, *featbf, *w1t, *w2t, *e1bf;
    cudaGetSymbolAddress((void**)&poolh,  g_poolt_h);
    cudaGetSymbolAddress((void**)&pooll,  g_poolt_l);
    cudaGetSymbolAddress((void**)&feat,   g_feat);
    cudaGetSymbolAddress((void**)&featbf, g_featbf);
    cudaGetSymbolAddress((void**)&w1t,    g_w1t);
    cudaGetSymbolAddress((void**)&w2t,    g_w2t);
    cudaGetSymbolAddress((void**)&wgT,    g_wgT);
    cudaGetSymbolAddress((void**)&gwp,    g_gw);
    cudaGetSymbolAddress((void**)&e1bf,   g_e1bf);

    cudaFuncSetAttribute(k_conv2_mma,   cudaFuncAttributeMaxDynamicSharedMemorySize, C2_SMEM);
    cudaFuncSetAttribute(k_gemm1_mma,   cudaFuncAttributeMaxDynamicSharedMemorySize, G1_SMEM);
    cudaFuncSetAttribute(k_expert2_mma, cudaFuncAttributeMaxDynamicSharedMemorySize, E2_SMEM);

    k_wgt<<<(10 * DIN + 255) / 256, 256>>>(Wg, Wglu, wgT);
    dim3 gW(DIN / 32, DH / 32, NEXP);
    k_w1_convert<<<gW, dim3(32, 8)>>>(W1e, w1t);
    dim3 gW2(DH / 32, DH / 32, NEXP);
    k_w2_convert<<<gW2, dim3(32, 8)>>>(W2e, w2t);
    k_conv1_mma<<<BATCH, 256>>>(x, conv1_w, conv1_b, poolh, pooll);
    k_conv2_mma<<<BATCH / 2, 256, C2_SMEM>>>(poolh, pooll, conv2_w, conv2_b, feat, featbf);
    k_router<<<BATCH / 8, 256>>>(feat, wgT, bg, bglu, gwp);
    dim3 g4(BATCH / 128, NEXP);
    k_gemm1_mma<<<g4, 256, G1_SMEM>>>(featbf, w1t, b1e, e1bf);
    k_expert2_mma<<<BATCH / 32, 256, E2_SMEM>>>(e1bf, w2t, b2e, gwp, Ws, bs, out);
}

// round 15
// speedup vs baseline: 1.2721x; 1.0624x over previous
#include <cuda_runtime.h>
#include <cuda_bf16.h>
#include <math.h>
#include <stdint.h>

#define BATCH 8192
#define DIN   3200
#define DH    128
#define NEXP  5
#define CHP   24      // channel pitch for pool tiles (48B rows: 16B-aligned, conflict-free)

// ---------------- scratch (static device memory; no allocation) ----------------
__device__ __nv_bfloat16 g_poolt_h[BATCH * 144 * CHP]; // conv1 out hi [B][pos][24]
__device__ __nv_bfloat16 g_poolt_l[BATCH * 144 * CHP]; // conv1 out lo
__device__ float g_feat[BATCH * DIN];                  // conv2 output fp32 (router)
__device__ __nv_bfloat16 g_featbf[BATCH * DIN];        // conv2 output bf16 (gemm1)
__device__ __nv_bfloat16 g_w1t[NEXP * DH * DIN];       // W1e transposed bf16 [5][128][3200]
__device__ __nv_bfloat16 g_w2t[NEXP * DH * DH];        // W2e transposed bf16 [5][g][h]
__device__ float g_wgT[10 * DIN];                      // [Wg|Wglu]^T fp32
__device__ float g_gw  [BATCH * NEXP];                 // routing weights [B,5]
__device__ __nv_bfloat16 g_e1bf[BATCH * NEXP * DH];    // expert layer-1 bf16 [B,640]

// =========================== PTX helpers (baseline ISA only) ====================
__device__ __forceinline__ uint32_t smem_u32(const void* p) {
    uint32_t a;
    asm("{ .reg .u64 t; cvta.to.shared.u64 t, %1; cvt.u32.u64 %0, t; }" : "=r"(a) : "l"(p));
    return a;
}
__device__ __forceinline__ void cp_async16(uint32_t dst, const void* src) {
    asm volatile("cp.async.cg.shared.global [%0], [%1], 16;" :: "r"(dst), "l"(src) : "memory");
}
#define CP_COMMIT() asm volatile("cp.async.commit_group;" ::: "memory")
#define CP_WAIT(n)  asm volatile("cp.async.wait_group %0;" :: "n"(n) : "memory")

__device__ __forceinline__ void ldsm_x4(uint32_t addr, uint32_t& r0, uint32_t& r1,
                                        uint32_t& r2, uint32_t& r3) {
    asm volatile("ldmatrix.sync.aligned.m8n8.x4.shared.b16 {%0,%1,%2,%3}, [%4];"
                 : "=r"(r0), "=r"(r1), "=r"(r2), "=r"(r3) : "r"(addr));
}
__device__ __forceinline__ void ldsm_x2(uint32_t addr, uint32_t& r0, uint32_t& r1) {
    asm volatile("ldmatrix.sync.aligned.m8n8.x2.shared.b16 {%0,%1}, [%2];"
                 : "=r"(r0), "=r"(r1) : "r"(addr));
}
__device__ __forceinline__ void mma_bf16(float* d, const uint32_t* a, const uint32_t* b) {
    asm volatile("mma.sync.aligned.m16n8k16.row.col.f32.bf16.bf16.f32 "
                 "{%0,%1,%2,%3}, {%4,%5,%6,%7}, {%8,%9}, {%0,%1,%2,%3};"
                 : "+f"(d[0]), "+f"(d[1]), "+f"(d[2]), "+f"(d[3])
                 : "r"(a[0]), "r"(a[1]), "r"(a[2]), "r"(a[3]), "r"(b[0]), "r"(b[1]));
}
__device__ __forceinline__ void mma_bf16_k8(float* d, const uint32_t* a, uint32_t b) {
    asm volatile("mma.sync.aligned.m16n8k8.row.col.f32.bf16.bf16.f32 "
                 "{%0,%1,%2,%3}, {%4,%5}, {%6}, {%0,%1,%2,%3};"
                 : "+f"(d[0]), "+f"(d[1]), "+f"(d[2]), "+f"(d[3])
                 : "r"(a[0]), "r"(a[1]), "r"(b));
}
__device__ __forceinline__ uint32_t bf16pack(float a, float b) {
    return (uint32_t)__bfloat16_as_ushort(__float2bfloat16(a)) |
           ((uint32_t)__bfloat16_as_ushort(__float2bfloat16(b)) << 16);
}

// ====== Kernel 1 (v3): conv1 (5x5) + ReLU + maxpool — direct-image HMMA k8 ======
// 1 image/CTA, 256 threads. No im2col: A-frag rows are contiguous 8-bf16 windows
// of the image. 4 planes (even/odd column phase x hi/lo split) make every lane's
// u32 load 4B-aligned. k=5..7 / pad columns are zero in B, so A garbage there is
// harmless (planes zero-initialized -> finite). 3-pass split-bf16 (fp32-exact).
#define C1_PSTR  1856            // even-phase -> odd-phase plane stride
#define C1_HILO  3712            // hi -> lo stride (2 planes)
#define C1_BHI   7424            // B hi: [5 ky][16 ch][8 k] bf16 = 1280
#define C1_BLO   8704
#define C1_OUT   9984            // f32 [576][18] = 41472
#define C1_SMEM  51456
__global__ void __launch_bounds__(256)
k_conv1_mma(const float* __restrict__ x,
            const float* __restrict__ w,      // [16][1][5][5]
            const float* __restrict__ bias,   // [16]
            __nv_bfloat16* __restrict__ ph,
            __nv_bfloat16* __restrict__ pl) {
    extern __shared__ __align__(16) unsigned char sm1[];
    uint32_t sb = smem_u32(sm1);
    int tid = threadIdx.x;
    int wpid = tid >> 5, lane = tid & 31;
    int b = blockIdx.x;

    // zero the 4 image planes (incl. pad columns; keeps garbage finite)
    for (int i = tid; i < 1856; i += 256) ((uint32_t*)sm1)[i] = 0;
    __syncthreads();

    // fill planes: pixel (r,c) -> E[r][c]; O[r][c-1] (shift-by-one copy)
    for (int i = tid; i < 784; i += 256) {
        int r = i / 28, c = i - (i / 28) * 28;
        float v = x[(size_t)b * 784 + i];
        __nv_bfloat16 h = __float2bfloat16(v);
        __nv_bfloat16 l = __float2bfloat16(v - __bfloat162float(h));
        *(__nv_bfloat16*)(sm1 + r * 64 + c * 2) = h;
        *(__nv_bfloat16*)(sm1 + C1_HILO + r * 64 + c * 2) = l;
        if (c >= 1) {
            *(__nv_bfloat16*)(sm1 + C1_PSTR + r * 64 + (c - 1) * 2) = h;
            *(__nv_bfloat16*)(sm1 + C1_PSTR + C1_HILO + r * 64 + (c - 1) * 2) = l;
        }
    }
    // fill B: [ky][ch][8k], k>=5 zero, hi/lo split
    for (int i = tid; i < 640; i += 256) {
        int ky = i >> 7, rem = i & 127, ch = rem >> 3, k = rem & 7;
        float v = (k < 5) ? w[ch * 25 + ky * 5 + k] : 0.0f;
        __nv_bfloat16 h = __float2bfloat16(v);
        *(__nv_bfloat16*)(sm1 + C1_BHI + ky * 256 + ch * 16 + k * 2) = h;
        *(__nv_bfloat16*)(sm1 + C1_BLO + ky * 256 + ch * 16 + k * 2) =
            __float2bfloat16(v - __bfloat162float(h));
    }
    __syncthreads();

    // preload B fragments: [ky][ntile], hi + lo
    uint32_t bhf[5][2], blf[5][2];
    {
        uint32_t ba = sb + C1_BHI + (lane & 15) * 16;
#pragma unroll
        for (int ky = 0; ky < 5; ky++) {
            ldsm_x2(ba + ky * 256, bhf[ky][0], bhf[ky][1]);
            ldsm_x2(ba + ky * 256 + 1280, blf[ky][0], blf[ky][1]);
        }
    }

    int g = lane >> 2, k2b = (lane & 3) * 4;
    int qr = lane >> 2, qc = (lane & 3) * 2;
    float* o = (float*)(sm1 + C1_OUT);

    // 36 m16-tiles over 8 warps, fully independent
    for (int t = wpid; t < 36; t += 8) {
        int m0 = t * 16;
        int p0 = m0 + g, p1 = p0 + 8;
        int oy0 = p0 / 24, ox0 = p0 - oy0 * 24;
        int oy1 = p1 / 24, ox1 = p1 - oy1 * 24;
        uint32_t off0 = (uint32_t)((ox0 & 1) * C1_PSTR + oy0 * 64 + (ox0 & ~1) * 2 + k2b);
        uint32_t off1 = (uint32_t)((ox1 & 1) * C1_PSTR + oy1 * 64 + (ox1 & ~1) * 2 + k2b);

        float acc[2][4];
#pragma unroll
        for (int n = 0; n < 2; n++)
#pragma unroll
            for (int q = 0; q < 4; q++) acc[n][q] = 0.0f;

#pragma unroll
        for (int ky = 0; ky < 5; ky++) {
            uint32_t ah[2], al[2];
            ah[0] = *(const uint32_t*)(sm1 + off0 + ky * 64);
            ah[1] = *(const uint32_t*)(sm1 + off1 + ky * 64);
            al[0] = *(const uint32_t*)(sm1 + C1_HILO + off0 + ky * 64);
            al[1] = *(const uint32_t*)(sm1 + C1_HILO + off1 + ky * 64);
#pragma unroll
            for (int n = 0; n < 2; n++) {
                mma_bf16_k8(acc[n], ah, bhf[ky][n]);
                mma_bf16_k8(acc[n], ah, blf[ky][n]);
                mma_bf16_k8(acc[n], al, bhf[ky][n]);
            }
        }
#pragma unroll
        for (int n = 0; n < 2; n++) {
            float2 v0 = {acc[n][0], acc[n][1]};
            float2 v1 = {acc[n][2], acc[n][3]};
            *(float2*)&o[(m0 + qr) * 18 + n * 8 + qc] = v0;
            *(float2*)&o[(m0 + 8 + qr) * 18 + n * 8 + qc] = v1;
        }
    }
    __syncthreads();

    // pool: 144 out-pos x 8 ch-pairs; relu(max4 + bias), hi/lo split store
    for (int i = tid; i < 1152; i += 256) {
        int opos = i >> 3, cp = (i & 7) * 2;
        int py = opos / 12, px = opos - py * 12;
        int cbase = (2 * py) * 24 + 2 * px;
        const float* r0 = &o[cbase * 18];
        const float* r1 = r0 + 18;
        const float* r2 = &o[(cbase + 24) * 18];
        const float* r3 = r2 + 18;
        float m0v = fmaxf(fmaxf(r0[cp], r1[cp]), fmaxf(r2[cp], r3[cp])) + __ldg(&bias[cp]);
        float m1v = fmaxf(fmaxf(r0[cp + 1], r1[cp + 1]), fmaxf(r2[cp + 1], r3[cp + 1]))
                    + __ldg(&bias[cp + 1]);
        m0v = fmaxf(m0v, 0.0f);
        m1v = fmaxf(m1v, 0.0f);
        __nv_bfloat16 h0 = __float2bfloat16(m0v), h1 = __float2bfloat16(m1v);
        int pbase = (b * 144 + opos) * CHP + cp;
        *(uint32_t*)(ph + pbase) =
            (uint32_t)__bfloat16_as_ushort(h0) | ((uint32_t)__bfloat16_as_ushort(h1) << 16);
        *(uint32_t*)(pl + pbase) =
            bf16pack(m0v - __bfloat162float(h0), m1v - __bfloat162float(h1));
    }
}

// ====== Kernel 2: conv2 via HMMA implicit conv, 3-pass split-bf16 (fp32-exact) ==
#define C2_POOLH 0
#define C2_POOLL 13824
#define C2_BHO   27648
#define C2_BLO   41472
#define C2_OUTF  0
#define C2_BIAS  55296
#define C2_SMEM  55424
__global__ void __launch_bounds__(256)
k_conv2_mma(const __nv_bfloat16* __restrict__ ph,
            const __nv_bfloat16* __restrict__ pl,
            const float* __restrict__ w2,     // [32][16][3][3]
            const float* __restrict__ bias,
            float* __restrict__ feat,
            __nv_bfloat16* __restrict__ featbf) {
    extern __shared__ __align__(16) unsigned char sm[];
    uint32_t sb = smem_u32(sm);
    int tid = threadIdx.x;
    int w8 = tid >> 5, lane = tid & 31;
    int b0 = blockIdx.x * 2;
    int img = w8 >> 2;
    int wbase = (w8 & 3) * 32;

    for (int c = tid; c < 1728; c += 256) {
        int im = c / 864; int r = c % 864; int plane = r / 432; int off = (r % 432) * 16;
        uint32_t dst = sb + (plane ? C2_POOLL : C2_POOLH) + im * 6912 + off;
        const __nv_bfloat16* src = (plane ? pl : ph) + (size_t)(b0 + im) * (144 * CHP);
        cp_async16(dst, (const char*)src + off);
    }
    CP_COMMIT();

    for (int i = tid; i < 4608; i += 256) {
        int tap = i >> 9; int oc = (i >> 4) & 31; int ch = i & 15;
        float v = w2[(oc * 16 + ch) * 9 + tap];
        __nv_bfloat16 h = __float2bfloat16(v);
        int off = ((tap * 32 + oc) * CHP + ch) * 2;
        *(__nv_bfloat16*)(sm + C2_BHO + off) = h;
        *(__nv_bfloat16*)(sm + C2_BLO + off) = __float2bfloat16(v - __bfloat162float(h));
    }
    if (tid < 32) *(float*)(sm + C2_BIAS + tid * 4) = bias[tid];
    CP_WAIT(0);
    __syncthreads();

    int posIdx[2];
#pragma unroll
    for (int mi = 0; mi < 2; mi++) {
        int pos = wbase + mi * 16 + (lane & 15);
        pos = min(pos, 99);
        posIdx[mi] = (pos / 10) * 12 + (pos % 10);
    }
    int chOff = (lane >> 4) * 16;
    uint32_t aBaseH = sb + C2_POOLH + img * 6912 + chOff;
    uint32_t aBaseL = sb + C2_POOLL + img * 6912 + chOff;
    int bRow = (lane & 7) + (lane >> 4) * 8;
    int bKb = ((lane >> 3) & 1) * 16;
    uint32_t bBaseH = sb + C2_BHO + bRow * (CHP * 2) + bKb;
    uint32_t bBaseL = sb + C2_BLO + bRow * (CHP * 2) + bKb;

    float acc[2][4][4];
#pragma unroll
    for (int i = 0; i < 2; i++)
#pragma unroll
        for (int j = 0; j < 4; j++)
#pragma unroll
            for (int q = 0; q < 4; q++) acc[i][j][q] = 0.0f;

    const int tapOff[9] = {0, 1, 2, 12, 13, 14, 24, 25, 26};
#pragma unroll
    for (int tap = 0; tap < 9; tap++) {
        int to = tapOff[tap] * (CHP * 2);
        uint32_t ah[2][4], al[2][4], bh[4][2], bl[4][2];
#pragma unroll
        for (int mi = 0; mi < 2; mi++) {
            ldsm_x4(aBaseH + posIdx[mi] * (CHP * 2) + to, ah[mi][0], ah[mi][1], ah[mi][2], ah[mi][3]);
            ldsm_x4(aBaseL + posIdx[mi] * (CHP * 2) + to, al[mi][0], al[mi][1], al[mi][2], al[mi][3]);
        }
#pragma unroll
        for (int j2 = 0; j2 < 2; j2++) {
            uint32_t off = (tap * 32 + j2 * 16) * (CHP * 2);
            ldsm_x4(bBaseH + off, bh[2 * j2][0], bh[2 * j2][1], bh[2 * j2 + 1][0], bh[2 * j2 + 1][1]);
            ldsm_x4(bBaseL + off, bl[2 * j2][0], bl[2 * j2][1], bl[2 * j2 + 1][0], bl[2 * j2 + 1][1]);
        }
#pragma unroll
        for (int mi = 0; mi < 2; mi++)
#pragma unroll
            for (int nj = 0; nj < 4; nj++) {
                mma_bf16(acc[mi][nj], ah[mi], bh[nj]);
                mma_bf16(acc[mi][nj], ah[mi], bl[nj]);
                mma_bf16(acc[mi][nj], al[mi], bh[nj]);
            }
    }

    __syncthreads();   // all smem reads done — OUTF may overwrite pool/weights

#pragma unroll
    for (int mi = 0; mi < 2; mi++) {
        int pr = wbase + mi * 16 + (lane >> 2);
#pragma unroll
        for (int nj = 0; nj < 4; nj++) {
            int c0 = nj * 8 + (lane & 3) * 2;
            float bb0 = *(float*)(sm + C2_BIAS + c0 * 4);
            float bb1 = *(float*)(sm + C2_BIAS + (c0 + 1) * 4);
            float* o = (float*)(sm + C2_OUTF) + img * 3616;
            if (pr < 100) {
                o[c0 * 113 + pr]       = fmaxf(acc[mi][nj][0] + bb0, 0.0f);
                o[(c0 + 1) * 113 + pr] = fmaxf(acc[mi][nj][1] + bb1, 0.0f);
            }
            if (pr + 8 < 100) {
                o[c0 * 113 + pr + 8]       = fmaxf(acc[mi][nj][2] + bb0, 0.0f);
                o[(c0 + 1) * 113 + pr + 8] = fmaxf(acc[mi][nj][3] + bb1, 0.0f);
            }
        }
    }
    __syncthreads();

    for (int i = tid; i < 3200; i += 256) {
        int im = i / 1600;
        int p2 = i - im * 1600;
        int oc = p2 / 50;
        int pos = (p2 - oc * 50) * 2;
        const float* o = (const float*)(sm + C2_OUTF) + im * 3616 + oc * 113 + pos;
        float v0 = o[0], v1 = o[1];
        size_t g = (size_t)(b0 + im) * DIN + oc * 100 + pos;
        float2 fv = {v0, v1};
        *(float2*)(feat + g) = fv;
        *(uint32_t*)(featbf + g) = bf16pack(v0, v1);
    }
}

// ================ Kernel 2b: W1e [5,3200,128] fp32 -> W1t [5,128,3200] bf16 =====
__global__ void k_w1_convert(const float* __restrict__ W1e,
                             __nv_bfloat16* __restrict__ W1t) {
    __shared__ float t[32][33];
    int e = blockIdx.z;
    int k0 = blockIdx.x * 32;
    int n0 = blockIdx.y * 32;
    int tx = threadIdx.x, ty = threadIdx.y;
    const float* Win = W1e + (size_t)e * DIN * DH;
    __nv_bfloat16* Wout = W1t + (size_t)e * DH * DIN;
#pragma unroll
    for (int yy = ty; yy < 32; yy += 8)
        t[yy][tx] = Win[(size_t)(k0 + yy) * DH + n0 + tx];
    __syncthreads();
#pragma unroll
    for (int yy = ty; yy < 32; yy += 8)
        Wout[(size_t)(n0 + yy) * DIN + k0 + tx] = __float2bfloat16(t[tx][yy]);
}

// ================ Kernel 2b': W2e [5,128,128] fp32 -> W2t [5][g][h] bf16 ========
__global__ void k_w2_convert(const float* __restrict__ W2e,
                             __nv_bfloat16* __restrict__ W2t) {
    __shared__ float t[32][33];
    int e = blockIdx.z;
    int h0 = blockIdx.x * 32;
    int g0 = blockIdx.y * 32;
    int tx = threadIdx.x, ty = threadIdx.y;
    const float* Win = W2e + (size_t)e * DH * DH;
    __nv_bfloat16* Wout = W2t + (size_t)e * DH * DH;
#pragma unroll
    for (int yy = ty; yy < 32; yy += 8)
        t[yy][tx] = Win[(h0 + yy) * DH + g0 + tx];
    __syncthreads();
#pragma unroll
    for (int yy = ty; yy < 32; yy += 8)
        Wout[(g0 + yy) * DH + h0 + tx] = __float2bfloat16(t[tx][yy]);
}

// ================ Kernel 2c: [Wg|Wglu] -> wgT [10][3200] fp32 ===================
__global__ void k_wgt(const float* __restrict__ Wg, const float* __restrict__ Wgl,
                      float* __restrict__ wgT) {
    int i = blockIdx.x * 256 + threadIdx.x;
    if (i >= 10 * DIN) return;
    int e = i / DIN, k = i % DIN;
    wgT[i] = (e < 5) ? Wg[k * 5 + e] : Wgl[k * 5 + (e - 5)];
}

// ================= Kernel 3: GLU router (fp32, coalesced) =======================
__global__ void k_router(const float* __restrict__ feat,
                         const float* __restrict__ wgT,
                         const float* __restrict__ bg, const float* __restrict__ bgl,
                         float* __restrict__ gw) {
    int warp = (blockIdx.x * blockDim.x + threadIdx.x) >> 5;
    int lane = threadIdx.x & 31;
    if (warp >= BATCH) return;
    const float4* f4 = (const float4*)(feat + (size_t)warp * DIN);
    float acc[10];
#pragma unroll
    for (int e = 0; e < 10; e++) acc[e] = 0.0f;
#pragma unroll 5
    for (int it = 0; it < 25; it++) {
        int k4 = it * 32 + lane;
        float4 fv = f4[k4];
#pragma unroll
        for (int e = 0; e < 10; e++) {
            float4 wv = ((const float4*)(wgT + e * DIN))[k4];
            acc[e] += fv.x * wv.x + fv.y * wv.y + fv.z * wv.z + fv.w * wv.w;
        }
    }
#pragma unroll
    for (int off = 16; off; off >>= 1)
#pragma unroll
        for (int e = 0; e < 10; e++)
            acc[e] += __shfl_down_sync(0xFFFFFFFFu, acc[e], off);

    if (lane == 0) {
        float gate[NEXP];
#pragma unroll
        for (int e = 0; e < NEXP; e++) {
            float g = acc[e] + bg[e];
            float s = 1.0f / (1.0f + expf(-(acc[5 + e] + bgl[e])));
            gate[e] = g * s;
        }
        float v0 = -1e30f, v1 = -1e30f, v2 = -1e30f;
        int i0 = 0, i1 = 0, i2 = 0;
#pragma unroll
        for (int e = 0; e < NEXP; e++) {
            float g = gate[e];
            if (g > v0)      { v2 = v1; i2 = i1; v1 = v0; i1 = i0; v0 = g; i0 = e; }
            else if (g > v1) { v2 = v1; i2 = i1; v1 = g;  i1 = e; }
            else if (g > v2) { v2 = g;  i2 = e; }
        }
        float e1 = expf(v1 - v0);
        float e2 = expf(v2 - v0);
        float inv = 1.0f / (1.0f + e1 + e2);
        float wout[NEXP];
#pragma unroll
        for (int e = 0; e < NEXP; e++) wout[e] = 0.0f;
        wout[i0] = inv; wout[i1] = e1 * inv; wout[i2] = e2 * inv;
#pragma unroll
        for (int e = 0; e < NEXP; e++) gw[warp * NEXP + e] = wout[e];
    }
}

// ===== Kernel 4: e1 = tanh(feat @ W1e + b1e) — HMMA, 3-stage cp.async pipeline ==
#define BKC   32
#define NTC   (DIN / BKC)          // 100 k-chunks
#define PITCH 80                   // bytes per 32-bf16 row
#define G1_TILE (128 * PITCH)      // 10240 per operand stage
#define G1_SMEM (6 * G1_TILE)      // 3 stages x (A + B) = 61440
__global__ void __launch_bounds__(256)
k_gemm1_mma(const __nv_bfloat16* __restrict__ A,
            const __nv_bfloat16* __restrict__ Bt,
            const float* __restrict__ b1e,
            __nv_bfloat16* __restrict__ E1bf) {     // [8192,640] bf16
    extern __shared__ __align__(128) unsigned char dsm[];
    uint32_t sA0 = smem_u32(dsm);
    uint32_t sB0 = sA0 + 3 * G1_TILE;

    int tid = threadIdx.x;
    int w = tid >> 5, lane = tid & 31;
    int wm = w & 3, wn = w >> 2;
    int mb = blockIdx.x, e = blockIdx.y;

    const __nv_bfloat16* Ab = A  + (size_t)(mb * 128) * DIN;
    const __nv_bfloat16* Bb = Bt + (size_t)e * DH * DIN;

    float acc[2][8][4];
#pragma unroll
    for (int i = 0; i < 2; i++)
#pragma unroll
        for (int j = 0; j < 8; j++)
#pragma unroll
            for (int q = 0; q < 4; q++) acc[i][j][q] = 0.0f;

    int lr = tid >> 1;
    int lc = (tid & 1) * 2;
    auto load_tile = [&](int t, int s) {
        int k0 = t * BKC;
        uint32_t aD = sA0 + s * G1_TILE + lr * PITCH + lc * 16;
        uint32_t bD = sB0 + s * G1_TILE + lr * PITCH + lc * 16;
        const __nv_bfloat16* aS = Ab + (size_t)lr * DIN + k0 + lc * 8;
        const __nv_bfloat16* bS = Bb + (size_t)lr * DIN + k0 + lc * 8;
        cp_async16(aD,      aS);
        cp_async16(aD + 16, aS + 8);
        cp_async16(bD,      bS);
        cp_async16(bD + 16, bS + 8);
    };

    load_tile(0, 0); CP_COMMIT();
    load_tile(1, 1); CP_COMMIT();

    int aRow = (lane & 7) + ((lane >> 3) & 1) * 8;
    int aKb  = (lane >> 4) * 16;
    int bRow = (lane & 7) + (lane >> 4) * 8;
    int bKb  = ((lane >> 3) & 1) * 16;

    int s = 0;                     // stage = t % 3
    for (int t = 0; t < NTC; t++) {
        CP_WAIT(1);                // tile t's group complete (t+1 may pend)
        __syncthreads();           // everyone done computing t-1 before refilling
        if (t + 2 < NTC) {
            int s2 = s + 2; if (s2 >= 3) s2 -= 3;
            load_tile(t + 2, s2);
        }
        CP_COMMIT();               // always commit (uniform group accounting)

        uint32_t aT = sA0 + s * G1_TILE;
        uint32_t bT = sB0 + s * G1_TILE;
#pragma unroll
        for (int ks = 0; ks < 2; ks++) {
            uint32_t a[2][4], b[8][2];
#pragma unroll
            for (int i = 0; i < 2; i++) {
                uint32_t addr = aT + (wm * 32 + i * 16 + aRow) * PITCH + ks * 32 + aKb;
                ldsm_x4(addr, a[i][0], a[i][1], a[i][2], a[i][3]);
            }
#pragma unroll
            for (int j2 = 0; j2 < 4; j2++) {
                uint32_t addr = bT + (wn * 64 + j2 * 16 + bRow) * PITCH + ks * 32 + bKb;
                ldsm_x4(addr, b[2 * j2][0], b[2 * j2][1], b[2 * j2 + 1][0], b[2 * j2 + 1][1]);
            }
#pragma unroll
            for (int i = 0; i < 2; i++)
#pragma unroll
                for (int j = 0; j < 8; j++)
                    mma_bf16(acc[i][j], a[i], b[j]);
        }
        if (++s == 3) s = 0;
    }

    const float* bias = b1e + e * DH;
    int qr = lane >> 2;
    int qc = (lane & 3) * 2;
#pragma unroll
    for (int i = 0; i < 2; i++) {
        int m0 = mb * 128 + wm * 32 + i * 16 + qr;
#pragma unroll
        for (int j = 0; j < 8; j++) {
            int c = wn * 64 + j * 8 + qc;
            float b0 = __ldg(&bias[c]);
            float b1 = __ldg(&bias[c + 1]);
            uint32_t p0 = bf16pack(tanhf(acc[i][j][0] + b0), tanhf(acc[i][j][1] + b1));
            uint32_t p1 = bf16pack(tanhf(acc[i][j][2] + b0), tanhf(acc[i][j][3] + b1));
            *(uint32_t*)(E1bf + (size_t)m0 * (NEXP * DH) + e * DH + c) = p0;
            *(uint32_t*)(E1bf + (size_t)(m0 + 8) * (NEXP * DH) + e * DH + c) = p1;
        }
    }
}

// ====== Kernel 5: expert-2 via HMMA bf16 + weighted combine + head + softmax ====
#define E2P   272                       // smem row pitch bytes (136 bf16)
#define E2_SA  0                        // A: 32 x 136 bf16 = 8704
#define E2_SB  8704                     // B: 128 x 136 bf16 = 34816
#define E2_MOE 43520                    // 32 x 128 f32 = 16384
#define E2_WS  59904                    // 1280 f32 = 5120
#define E2_GW  65024                    // 160 f32 = 640
#define E2_LOG 65664                    // 320 f32 = 1280
#define E2_SMEM 66944
__global__ void __launch_bounds__(256)
k_expert2_mma(const __nv_bfloat16* __restrict__ E1bf,   // [8192,640]
              const __nv_bfloat16* __restrict__ W2t,    // [5][g][h]
              const float* __restrict__ b2e,            // [5,128]
              const float* __restrict__ gw,             // [8192,5]
              const float* __restrict__ Ws,             // [128,10]
              const float* __restrict__ bs,             // [10]
              float* __restrict__ out) {                // [8192,10]
    extern __shared__ __align__(16) unsigned char dsm[];
    uint32_t sb = smem_u32(dsm);
    int tid = threadIdx.x;
    int w = tid >> 5, lane = tid & 31;
    int b0 = blockIdx.x * 32;

    float* s_ws  = (float*)(dsm + E2_WS);
    float* s_gw  = (float*)(dsm + E2_GW);
    float* s_moe = (float*)(dsm + E2_MOE);
    float* s_log = (float*)(dsm + E2_LOG);

    for (int i = tid; i < 1280; i += 256) s_ws[i] = Ws[i];
    for (int i = tid; i < 160; i += 256)  s_gw[i] = gw[b0 * NEXP + i];

    int aRow = (lane & 7) + ((lane >> 3) & 1) * 8;
    int aKb  = (lane >> 4) * 16;
    int bRow = (lane & 7) + (lane >> 4) * 8 + w * 16;
    int bKb  = ((lane >> 3) & 1) * 16;

    float moe[2][2][4];
#pragma unroll
    for (int i = 0; i < 2; i++)
#pragma unroll
        for (int j = 0; j < 2; j++)
#pragma unroll
            for (int q = 0; q < 4; q++) moe[i][j][q] = 0.0f;

    for (int e = 0; e < NEXP; e++) {
        __syncthreads();   // prior compute done before overwriting tiles
        for (int c = tid; c < 512; c += 256) {
            int r = c >> 4, ck = c & 15;
            cp_async16(sb + E2_SA + r * E2P + ck * 16,
                       E1bf + (size_t)(b0 + r) * (NEXP * DH) + e * DH + ck * 8);
        }
        for (int c = tid; c < 2048; c += 256) {
            int r = c >> 4, ck = c & 15;
            cp_async16(sb + E2_SB + r * E2P + ck * 16,
                       W2t + (size_t)e * DH * DH + r * DH + ck * 8);
        }
        CP_COMMIT(); CP_WAIT(0);
        __syncthreads();

        float acc[2][2][4];
#pragma unroll
        for (int i = 0; i < 2; i++)
#pragma unroll
            for (int j = 0; j < 2; j++)
#pragma unroll
                for (int q = 0; q < 4; q++) acc[i][j][q] = 0.0f;

#pragma unroll
        for (int k16 = 0; k16 < 8; k16++) {
            uint32_t a[2][4], b[2][2];
#pragma unroll
            for (int i = 0; i < 2; i++)
                ldsm_x4(sb + E2_SA + (i * 16 + aRow) * E2P + k16 * 32 + aKb,
                        a[i][0], a[i][1], a[i][2], a[i][3]);
            ldsm_x4(sb + E2_SB + bRow * E2P + k16 * 32 + bKb,
                    b[0][0], b[0][1], b[1][0], b[1][1]);
#pragma unroll
            for (int i = 0; i < 2; i++)
#pragma unroll
                for (int j = 0; j < 2; j++)
                    mma_bf16(acc[i][j], a[i], b[j]);
        }

#pragma unroll
        for (int i = 0; i < 2; i++)
#pragma unroll
            for (int j = 0; j < 2; j++)
#pragma unroll
                for (int q = 0; q < 4; q++) {
                    int row = i * 16 + (lane >> 2) + ((q >> 1) ? 8 : 0);
                    int g = w * 16 + j * 8 + (lane & 3) * 2 + (q & 1);
                    float pre = acc[i][j][q] + __ldg(&b2e[e * DH + g]);
                    moe[i][j][q] += s_gw[row * NEXP + e] * tanhf(pre);
                }
    }

    __syncthreads();
#pragma unroll
    for (int i = 0; i < 2; i++)
#pragma unroll
        for (int j = 0; j < 2; j++)
#pragma unroll
            for (int q = 0; q < 4; q++) {
                int row = i * 16 + (lane >> 2) + ((q >> 1) ? 8 : 0);
                int g = w * 16 + j * 8 + (lane & 3) * 2 + (q & 1);
                s_moe[row * DH + g] = moe[i][j][q];
            }
    __syncthreads();

    for (int i = tid; i < 320; i += 256) {
        int r = i / 10, c = i % 10;
        float a = __ldg(&bs[c]);
#pragma unroll 16
        for (int hh = 0; hh < 128; hh++)
            a += s_moe[r * DH + hh] * s_ws[hh * 10 + c];
        s_log[r * 10 + c] = a;
    }
    __syncthreads();
    if (tid < 32) {
        int r = tid;
        float m = -1e30f;
#pragma unroll
        for (int c = 0; c < 10; c++) m = fmaxf(m, s_log[r * 10 + c]);
        float ex[10], ssum = 0.0f;
#pragma unroll
        for (int c = 0; c < 10; c++) { ex[c] = expf(s_log[r * 10 + c] - m); ssum += ex[c]; }
        float inv = 1.0f / ssum;
        float* orow = out + (size_t)(b0 + r) * 10;
#pragma unroll
        for (int c = 0; c < 10; c++) orow[c] = ex[c] * inv;
    }
}

// =============================== launcher =======================================
extern "C" void kernel_launch(void* const* d_in, const int* in_sizes, int n_in,
                              void* d_out, int out_size) {
    const float* x       = (const float*)d_in[0];
    const float* conv1_w = (const float*)d_in[1];
    const float* conv1_b = (const float*)d_in[2];
    const float* conv2_w = (const float*)d_in[3];
    const float* conv2_b = (const float*)d_in[4];
    const float* Wg      = (const float*)d_in[5];
    const float* bg      = (const float*)d_in[6];
    const float* Wglu    = (const float*)d_in[7];
    const float* bglu    = (const float*)d_in[8];
    const float* W1e     = (const float*)d_in[9];
    const float* b1e     = (const float*)d_in[10];
    const float* W2e     = (const float*)d_in[11];
    const float* b2e     = (const float*)d_in[12];
    const float* Ws      = (const float*)d_in[13];
    const float* bs      = (const float*)d_in[14];
    float* out = (float*)d_out;

    float *feat, *wgT, *gwp;
    __nv_bfloat16 *poolh, *pooll, *featbf, *w1t, *w2t, *e1bf;
    cudaGetSymbolAddress((void**)&poolh,  g_poolt_h);
    cudaGetSymbolAddress((void**)&pooll,  g_poolt_l);
    cudaGetSymbolAddress((void**)&feat,   g_feat);
    cudaGetSymbolAddress((void**)&featbf, g_featbf);
    cudaGetSymbolAddress((void**)&w1t,    g_w1t);
    cudaGetSymbolAddress((void**)&w2t,    g_w2t);
    cudaGetSymbolAddress((void**)&wgT,    g_wgT);
    cudaGetSymbolAddress((void**)&gwp,    g_gw);
    cudaGetSymbolAddress((void**)&e1bf,   g_e1bf);

    cudaFuncSetAttribute(k_conv1_mma,   cudaFuncAttributeMaxDynamicSharedMemorySize, C1_SMEM);
    cudaFuncSetAttribute(k_conv2_mma,   cudaFuncAttributeMaxDynamicSharedMemorySize, C2_SMEM);
    cudaFuncSetAttribute(k_gemm1_mma,   cudaFuncAttributeMaxDynamicSharedMemorySize, G1_SMEM);
    cudaFuncSetAttribute(k_expert2_mma, cudaFuncAttributeMaxDynamicSharedMemorySize, E2_SMEM);

    k_wgt<<<(10 * DIN + 255) / 256, 256>>>(Wg, Wglu, wgT);
    dim3 gW(DIN / 32, DH / 32, NEXP);
    k_w1_convert<<<gW, dim3(32, 8)>>>(W1e, w1t);
    dim3 gW2(DH / 32, DH / 32, NEXP);
    k_w2_convert<<<gW2, dim3(32, 8)>>>(W2e, w2t);
    k_conv1_mma<<<BATCH, 256, C1_SMEM>>>(x, conv1_w, conv1_b, poolh, pooll);
    k_conv2_mma<<<BATCH / 2, 256, C2_SMEM>>>(poolh, pooll, conv2_w, conv2_b, feat, featbf);
    k_router<<<BATCH / 8, 256>>>(feat, wgT, bg, bglu, gwp);
    dim3 g4(BATCH / 128, NEXP);
    k_gemm1_mma<<<g4, 256, G1_SMEM>>>(featbf, w1t, b1e, e1bf);
    k_expert2_mma<<<BATCH / 32, 256, E2_SMEM>>>(e1bf, w2t, b2e, gwp, Ws, bs, out);
}

// round 16
// speedup vs baseline: 1.3450x; 1.0573x over previous
#include <cuda_runtime.h>
#include <cuda_bf16.h>
#include <math.h>
#include <stdint.h>

#define BATCH 8192
#define DIN   3200
#define DH    128
#define NEXP  5
#define CHP   24      // channel pitch for pool tiles (48B rows: 16B-aligned, conflict-free)

// ---------------- scratch (static device memory; no allocation) ----------------
__device__ __nv_bfloat16 g_poolt_h[BATCH * 144 * CHP]; // conv1 out hi [B][pos][24]
__device__ __nv_bfloat16 g_poolt_l[BATCH * 144 * CHP]; // conv1 out lo
__device__ float g_feat[BATCH * DIN];                  // conv2 output fp32 (router)
__device__ __nv_bfloat16 g_featbf[BATCH * DIN];        // conv2 output bf16 (gemm1)
__device__ __nv_bfloat16 g_w1t[NEXP * DH * DIN];       // W1e transposed bf16 [5][128][3200]
__device__ __nv_bfloat16 g_w2t[NEXP * DH * DH];        // W2e transposed bf16 [5][g][h]
__device__ float g_wgT[10 * DIN];                      // [Wg|Wglu]^T fp32
__device__ float g_gw  [BATCH * NEXP];                 // routing weights [B,5]
__device__ __nv_bfloat16 g_e1bf[BATCH * NEXP * DH];    // expert layer-1 bf16 [B,640]

// =========================== PTX helpers (baseline ISA only) ====================
__device__ __forceinline__ uint32_t smem_u32(const void* p) {
    uint32_t a;
    asm("{ .reg .u64 t; cvta.to.shared.u64 t, %1; cvt.u32.u64 %0, t; }" : "=r"(a) : "l"(p));
    return a;
}
__device__ __forceinline__ void cp_async16(uint32_t dst, const void* src) {
    asm volatile("cp.async.cg.shared.global [%0], [%1], 16;" :: "r"(dst), "l"(src) : "memory");
}
#define CP_COMMIT() asm volatile("cp.async.commit_group;" ::: "memory")
#define CP_WAIT(n)  asm volatile("cp.async.wait_group %0;" :: "n"(n) : "memory")

__device__ __forceinline__ void ldsm_x4(uint32_t addr, uint32_t& r0, uint32_t& r1,
                                        uint32_t& r2, uint32_t& r3) {
    asm volatile("ldmatrix.sync.aligned.m8n8.x4.shared.b16 {%0,%1,%2,%3}, [%4];"
                 : "=r"(r0), "=r"(r1), "=r"(r2), "=r"(r3) : "r"(addr));
}
__device__ __forceinline__ void ldsm_x2(uint32_t addr, uint32_t& r0, uint32_t& r1) {
    asm volatile("ldmatrix.sync.aligned.m8n8.x2.shared.b16 {%0,%1}, [%2];"
                 : "=r"(r0), "=r"(r1) : "r"(addr));
}
__device__ __forceinline__ void mma_bf16(float* d, const uint32_t* a, const uint32_t* b) {
    asm volatile("mma.sync.aligned.m16n8k16.row.col.f32.bf16.bf16.f32 "
                 "{%0,%1,%2,%3}, {%4,%5,%6,%7}, {%8,%9}, {%0,%1,%2,%3};"
                 : "+f"(d[0]), "+f"(d[1]), "+f"(d[2]), "+f"(d[3])
                 : "r"(a[0]), "r"(a[1]), "r"(a[2]), "r"(a[3]), "r"(b[0]), "r"(b[1]));
}
__device__ __forceinline__ void mma_bf16_k8(float* d, const uint32_t* a, uint32_t b) {
    asm volatile("mma.sync.aligned.m16n8k8.row.col.f32.bf16.bf16.f32 "
                 "{%0,%1,%2,%3}, {%4,%5}, {%6}, {%0,%1,%2,%3};"
                 : "+f"(d[0]), "+f"(d[1]), "+f"(d[2]), "+f"(d[3])
                 : "r"(a[0]), "r"(a[1]), "r"(b));
}
__device__ __forceinline__ uint32_t bf16pack(float a, float b) {
    return (uint32_t)__bfloat16_as_ushort(__float2bfloat16(a)) |
           ((uint32_t)__bfloat16_as_ushort(__float2bfloat16(b)) << 16);
}

// ====== Kernel 1 (v4): conv1 + ReLU + maxpool — k16 HMMA, register pooling ======
// 1 image/CTA, 192 threads (6 warps). Warp w owns pool rows {2w, 2w+1}; each pool
// row = 3 m16 tiles (48 conv positions). ky-pairs packed into k16 MMAs (k0-7 =
// img row r, k8-15 = row r+1), ky=4 as k8. 2x2 maxpool done in registers:
// adjacent-m max via shfl_xor(4), cross-conv-row max via q01/q23 register pairs.
// 3-pass split-bf16 (fp32-exact). smem ~10KB, no MMA/pool barriers.
#define C1_PSTR  1856            // even-phase -> odd-phase plane stride
#define C1_HILO  3712            // hi -> lo plane stride
#define C1_BHI   7424            // B hi: [2 kp][16 ch][16 k] = 1024B, then ky4 [16][8] = 256B
#define C1_BLO   8704            // B lo (same layout)
__global__ void __launch_bounds__(192)
k_conv1_mma(const float* __restrict__ x,
            const float* __restrict__ w,      // [16][1][5][5]
            const float* __restrict__ bias,   // [16]
            __nv_bfloat16* __restrict__ ph,
            __nv_bfloat16* __restrict__ pl) {
    __shared__ __align__(16) unsigned char sm1[9984];
    uint32_t sb = smem_u32(sm1);
    int tid = threadIdx.x;
    int wpid = tid >> 5, lane = tid & 31;
    int b = blockIdx.x;

    // zero the 4 image planes (keeps pad/garbage columns finite)
    for (int i = tid; i < 1856; i += 192) ((uint32_t*)sm1)[i] = 0;
    __syncthreads();

    // fill planes: pixel (r,c) -> E[r][c]; O[r][c-1] (shift-by-one copy)
    for (int i = tid; i < 784; i += 192) {
        int r = i / 28, c = i - (i / 28) * 28;
        float v = x[(size_t)b * 784 + i];
        __nv_bfloat16 h = __float2bfloat16(v);
        __nv_bfloat16 l = __float2bfloat16(v - __bfloat162float(h));
        *(__nv_bfloat16*)(sm1 + r * 64 + c * 2) = h;
        *(__nv_bfloat16*)(sm1 + C1_HILO + r * 64 + c * 2) = l;
        if (c >= 1) {
            *(__nv_bfloat16*)(sm1 + C1_PSTR + r * 64 + (c - 1) * 2) = h;
            *(__nv_bfloat16*)(sm1 + C1_PSTR + C1_HILO + r * 64 + (c - 1) * 2) = l;
        }
    }
    // fill B: kp blocks [kp][ch][16] (k = kyL*8+kx, kx>=5 zero) + ky4 [ch][8]
    for (int i = tid; i < 640; i += 192) {
        float v = 0.0f;
        int off;
        if (i < 512) {
            int kp = i >> 8, ch = (i >> 4) & 15, k = i & 15;
            int kyL = k >> 3, kx = k & 7;
            if (kx < 5) v = w[ch * 25 + (2 * kp + kyL) * 5 + kx];
            off = kp * 512 + ch * 32 + k * 2;
        } else {
            int j = i - 512, ch = j >> 3, kx = j & 7;
            if (kx < 5) v = w[ch * 25 + 20 + kx];
            off = 1024 + ch * 16 + kx * 2;
        }
        __nv_bfloat16 h = __float2bfloat16(v);
        *(__nv_bfloat16*)(sm1 + C1_BHI + off) = h;
        *(__nv_bfloat16*)(sm1 + C1_BLO + off) =
            __float2bfloat16(v - __bfloat162float(h));
    }
    __syncthreads();

    // preload B fragments
    uint32_t bh16[2][2][2], bl16[2][2][2];   // [kp][n][reg]
    uint32_t bh8[2], bl8[2];                 // [n]
    {
        int bRow = (lane & 7) + (lane >> 4) * 8;
        int bKb  = ((lane >> 3) & 1) * 16;
#pragma unroll
        for (int kp = 0; kp < 2; kp++) {
            ldsm_x4(sb + C1_BHI + kp * 512 + bRow * 32 + bKb,
                    bh16[kp][0][0], bh16[kp][0][1], bh16[kp][1][0], bh16[kp][1][1]);
            ldsm_x4(sb + C1_BLO + kp * 512 + bRow * 32 + bKb,
                    bl16[kp][0][0], bl16[kp][0][1], bl16[kp][1][0], bl16[kp][1][1]);
        }
        uint32_t ba8 = (lane & 15) * 16;
        ldsm_x2(sb + C1_BHI + 1024 + ba8, bh8[0], bh8[1]);
        ldsm_x2(sb + C1_BLO + 1024 + ba8, bl8[0], bl8[1]);
    }

    int g = lane >> 2, k2b = (lane & 3) * 4;
    bool active = (lane & 4) == 0;           // even group
    int v4i = lane >> 3;                     // 0..3 (px offset within combo)
    int c0 = (lane & 3) * 2;

#pragma unroll
    for (int pr = 0; pr < 2; pr++) {
        int py = wpid * 2 + pr;
        float acc[3][2][4];
#pragma unroll
        for (int j = 0; j < 3; j++)
#pragma unroll
            for (int n = 0; n < 2; n++)
#pragma unroll
                for (int q = 0; q < 4; q++) acc[j][n][q] = 0.0f;

#pragma unroll
        for (int j = 0; j < 3; j++) {
            int p0 = 48 * py + j * 16 + g;
            int p1 = p0 + 8;
            int oy0 = p0 / 24, ox0 = p0 - oy0 * 24;
            int oy1 = p1 / 24, ox1 = p1 - oy1 * 24;
            uint32_t off0 = (uint32_t)((ox0 & 1) * C1_PSTR + oy0 * 64 + (ox0 & ~1) * 2 + k2b);
            uint32_t off1 = (uint32_t)((ox1 & 1) * C1_PSTR + oy1 * 64 + (ox1 & ~1) * 2 + k2b);
#pragma unroll
            for (int kp = 0; kp < 2; kp++) {
                uint32_t ah[4], al[4];
                ah[0] = *(const uint32_t*)(sm1 + off0 + (2 * kp) * 64);
                ah[1] = *(const uint32_t*)(sm1 + off1 + (2 * kp) * 64);
                ah[2] = *(const uint32_t*)(sm1 + off0 + (2 * kp + 1) * 64);
                ah[3] = *(const uint32_t*)(sm1 + off1 + (2 * kp + 1) * 64);
                al[0] = *(const uint32_t*)(sm1 + C1_HILO + off0 + (2 * kp) * 64);
                al[1] = *(const uint32_t*)(sm1 + C1_HILO + off1 + (2 * kp) * 64);
                al[2] = *(const uint32_t*)(sm1 + C1_HILO + off0 + (2 * kp + 1) * 64);
                al[3] = *(const uint32_t*)(sm1 + C1_HILO + off1 + (2 * kp + 1) * 64);
#pragma unroll
                for (int n = 0; n < 2; n++) {
                    mma_bf16(acc[j][n], ah, bh16[kp][n]);
                    mma_bf16(acc[j][n], ah, bl16[kp][n]);
                    mma_bf16(acc[j][n], al, bh16[kp][n]);
                }
            }
            {   // ky = 4 (k8)
                uint32_t av[2], alv[2];
                av[0]  = *(const uint32_t*)(sm1 + off0 + 4 * 64);
                av[1]  = *(const uint32_t*)(sm1 + off1 + 4 * 64);
                alv[0] = *(const uint32_t*)(sm1 + C1_HILO + off0 + 4 * 64);
                alv[1] = *(const uint32_t*)(sm1 + C1_HILO + off1 + 4 * 64);
#pragma unroll
                for (int n = 0; n < 2; n++) {
                    mma_bf16_k8(acc[j][n], av, bh8[n]);
                    mma_bf16_k8(acc[j][n], av, bl8[n]);
                    mma_bf16_k8(acc[j][n], alv, bh8[n]);
                }
            }
        }

        // register pooling: combos {T0.q01,T1.q23}, {T0.q23,T2.q01}, {T1.q01,T2.q23}
        const int ta[3] = {0, 0, 1}, qa[3] = {0, 2, 0};
        const int tb[3] = {1, 2, 2}, qb[3] = {2, 0, 2};
#pragma unroll
        for (int n = 0; n < 2; n++) {
#pragma unroll
            for (int cm = 0; cm < 3; cm++) {
                float t0 = fmaxf(acc[ta[cm]][n][qa[cm]],     acc[tb[cm]][n][qb[cm]]);
                float t1 = fmaxf(acc[ta[cm]][n][qa[cm] + 1], acc[tb[cm]][n][qb[cm] + 1]);
                t0 = fmaxf(t0, __shfl_xor_sync(0xFFFFFFFFu, t0, 4));
                t1 = fmaxf(t1, __shfl_xor_sync(0xFFFFFFFFu, t1, 4));
                if (active) {
                    int px = cm * 4 + v4i;
                    int ch = n * 8 + c0;
                    float m0v = fmaxf(t0 + __ldg(&bias[ch]), 0.0f);
                    float m1v = fmaxf(t1 + __ldg(&bias[ch + 1]), 0.0f);
                    __nv_bfloat16 h0 = __float2bfloat16(m0v), h1 = __float2bfloat16(m1v);
                    int pbase = (b * 144 + py * 12 + px) * CHP + ch;
                    *(uint32_t*)(ph + pbase) =
                        (uint32_t)__bfloat16_as_ushort(h0) |
                        ((uint32_t)__bfloat16_as_ushort(h1) << 16);
                    *(uint32_t*)(pl + pbase) =
                        bf16pack(m0v - __bfloat162float(h0), m1v - __bfloat162float(h1));
                }
            }
        }
    }
}

// ====== Kernel 2: conv2 via HMMA implicit conv, 3-pass split-bf16 (fp32-exact) ==
#define C2_POOLH 0
#define C2_POOLL 13824
#define C2_BHO   27648
#define C2_BLO   41472
#define C2_OUTF  0
#define C2_BIAS  55296
#define C2_SMEM  55424
__global__ void __launch_bounds__(256)
k_conv2_mma(const __nv_bfloat16* __restrict__ ph,
            const __nv_bfloat16* __restrict__ pl,
            const float* __restrict__ w2,     // [32][16][3][3]
            const float* __restrict__ bias,
            float* __restrict__ feat,
            __nv_bfloat16* __restrict__ featbf) {
    extern __shared__ __align__(16) unsigned char sm[];
    uint32_t sb = smem_u32(sm);
    int tid = threadIdx.x;
    int w8 = tid >> 5, lane = tid & 31;
    int b0 = blockIdx.x * 2;
    int img = w8 >> 2;
    int wbase = (w8 & 3) * 32;

    for (int c = tid; c < 1728; c += 256) {
        int im = c / 864; int r = c % 864; int plane = r / 432; int off = (r % 432) * 16;
        uint32_t dst = sb + (plane ? C2_POOLL : C2_POOLH) + im * 6912 + off;
        const __nv_bfloat16* src = (plane ? pl : ph) + (size_t)(b0 + im) * (144 * CHP);
        cp_async16(dst, (const char*)src + off);
    }
    CP_COMMIT();

    for (int i = tid; i < 4608; i += 256) {
        int tap = i >> 9; int oc = (i >> 4) & 31; int ch = i & 15;
        float v = w2[(oc * 16 + ch) * 9 + tap];
        __nv_bfloat16 h = __float2bfloat16(v);
        int off = ((tap * 32 + oc) * CHP + ch) * 2;
        *(__nv_bfloat16*)(sm + C2_BHO + off) = h;
        *(__nv_bfloat16*)(sm + C2_BLO + off) = __float2bfloat16(v - __bfloat162float(h));
    }
    if (tid < 32) *(float*)(sm + C2_BIAS + tid * 4) = bias[tid];
    CP_WAIT(0);
    __syncthreads();

    int posIdx[2];
#pragma unroll
    for (int mi = 0; mi < 2; mi++) {
        int pos = wbase + mi * 16 + (lane & 15);
        pos = min(pos, 99);
        posIdx[mi] = (pos / 10) * 12 + (pos % 10);
    }
    int chOff = (lane >> 4) * 16;
    uint32_t aBaseH = sb + C2_POOLH + img * 6912 + chOff;
    uint32_t aBaseL = sb + C2_POOLL + img * 6912 + chOff;
    int bRow = (lane & 7) + (lane >> 4) * 8;
    int bKb = ((lane >> 3) & 1) * 16;
    uint32_t bBaseH = sb + C2_BHO + bRow * (CHP * 2) + bKb;
    uint32_t bBaseL = sb + C2_BLO + bRow * (CHP * 2) + bKb;

    float acc[2][4][4];
#pragma unroll
    for (int i = 0; i < 2; i++)
#pragma unroll
        for (int j = 0; j < 4; j++)
#pragma unroll
            for (int q = 0; q < 4; q++) acc[i][j][q] = 0.0f;

    const int tapOff[9] = {0, 1, 2, 12, 13, 14, 24, 25, 26};
#pragma unroll
    for (int tap = 0; tap < 9; tap++) {
        int to = tapOff[tap] * (CHP * 2);
        uint32_t ah[2][4], al[2][4], bh[4][2], bl[4][2];
#pragma unroll
        for (int mi = 0; mi < 2; mi++) {
            ldsm_x4(aBaseH + posIdx[mi] * (CHP * 2) + to, ah[mi][0], ah[mi][1], ah[mi][2], ah[mi][3]);
            ldsm_x4(aBaseL + posIdx[mi] * (CHP * 2) + to, al[mi][0], al[mi][1], al[mi][2], al[mi][3]);
        }
#pragma unroll
        for (int j2 = 0; j2 < 2; j2++) {
            uint32_t off = (tap * 32 + j2 * 16) * (CHP * 2);
            ldsm_x4(bBaseH + off, bh[2 * j2][0], bh[2 * j2][1], bh[2 * j2 + 1][0], bh[2 * j2 + 1][1]);
            ldsm_x4(bBaseL + off, bl[2 * j2][0], bl[2 * j2][1], bl[2 * j2 + 1][0], bl[2 * j2 + 1][1]);
        }
#pragma unroll
        for (int mi = 0; mi < 2; mi++)
#pragma unroll
            for (int nj = 0; nj < 4; nj++) {
                mma_bf16(acc[mi][nj], ah[mi], bh[nj]);
                mma_bf16(acc[mi][nj], ah[mi], bl[nj]);
                mma_bf16(acc[mi][nj], al[mi], bh[nj]);
            }
    }

    __syncthreads();   // all smem reads done — OUTF may overwrite pool/weights

#pragma unroll
    for (int mi = 0; mi < 2; mi++) {
        int pr = wbase + mi * 16 + (lane >> 2);
#pragma unroll
        for (int nj = 0; nj < 4; nj++) {
            int c0 = nj * 8 + (lane & 3) * 2;
            float bb0 = *(float*)(sm + C2_BIAS + c0 * 4);
            float bb1 = *(float*)(sm + C2_BIAS + (c0 + 1) * 4);
            float* o = (float*)(sm + C2_OUTF) + img * 3616;
            if (pr < 100) {
                o[c0 * 113 + pr]       = fmaxf(acc[mi][nj][0] + bb0, 0.0f);
                o[(c0 + 1) * 113 + pr] = fmaxf(acc[mi][nj][1] + bb1, 0.0f);
            }
            if (pr + 8 < 100) {
                o[c0 * 113 + pr + 8]       = fmaxf(acc[mi][nj][2] + bb0, 0.0f);
                o[(c0 + 1) * 113 + pr + 8] = fmaxf(acc[mi][nj][3] + bb1, 0.0f);
            }
        }
    }
    __syncthreads();

    for (int i = tid; i < 3200; i += 256) {
        int im = i / 1600;
        int p2 = i - im * 1600;
        int oc = p2 / 50;
        int pos = (p2 - oc * 50) * 2;
        const float* o = (const float*)(sm + C2_OUTF) + im * 3616 + oc * 113 + pos;
        float v0 = o[0], v1 = o[1];
        size_t g = (size_t)(b0 + im) * DIN + oc * 100 + pos;
        float2 fv = {v0, v1};
        *(float2*)(feat + g) = fv;
        *(uint32_t*)(featbf + g) = bf16pack(v0, v1);
    }
}

// ================ Kernel 2b: W1e [5,3200,128] fp32 -> W1t [5,128,3200] bf16 =====
__global__ void k_w1_convert(const float* __restrict__ W1e,
                             __nv_bfloat16* __restrict__ W1t) {
    __shared__ float t[32][33];
    int e = blockIdx.z;
    int k0 = blockIdx.x * 32;
    int n0 = blockIdx.y * 32;
    int tx = threadIdx.x, ty = threadIdx.y;
    const float* Win = W1e + (size_t)e * DIN * DH;
    __nv_bfloat16* Wout = W1t + (size_t)e * DH * DIN;
#pragma unroll
    for (int yy = ty; yy < 32; yy += 8)
        t[yy][tx] = Win[(size_t)(k0 + yy) * DH + n0 + tx];
    __syncthreads();
#pragma unroll
    for (int yy = ty; yy < 32; yy += 8)
        Wout[(size_t)(n0 + yy) * DIN + k0 + tx] = __float2bfloat16(t[tx][yy]);
}

// ================ Kernel 2b': W2e [5,128,128] fp32 -> W2t [5][g][h] bf16 ========
__global__ void k_w2_convert(const float* __restrict__ W2e,
                             __nv_bfloat16* __restrict__ W2t) {
    __shared__ float t[32][33];
    int e = blockIdx.z;
    int h0 = blockIdx.x * 32;
    int g0 = blockIdx.y * 32;
    int tx = threadIdx.x, ty = threadIdx.y;
    const float* Win = W2e + (size_t)e * DH * DH;
    __nv_bfloat16* Wout = W2t + (size_t)e * DH * DH;
#pragma unroll
    for (int yy = ty; yy < 32; yy += 8)
        t[yy][tx] = Win[(h0 + yy) * DH + g0 + tx];
    __syncthreads();
#pragma unroll
    for (int yy = ty; yy < 32; yy += 8)
        Wout[(g0 + yy) * DH + h0 + tx] = __float2bfloat16(t[tx][yy]);
}

// ================ Kernel 2c: [Wg|Wglu] -> wgT [10][3200] fp32 ===================
__global__ void k_wgt(const float* __restrict__ Wg, const float* __restrict__ Wgl,
                      float* __restrict__ wgT) {
    int i = blockIdx.x * 256 + threadIdx.x;
    if (i >= 10 * DIN) return;
    int e = i / DIN, k = i % DIN;
    wgT[i] = (e < 5) ? Wg[k * 5 + e] : Wgl[k * 5 + (e - 5)];
}

// ================= Kernel 3: GLU router (fp32, coalesced) =======================
__global__ void k_router(const float* __restrict__ feat,
                         const float* __restrict__ wgT,
                         const float* __restrict__ bg, const float* __restrict__ bgl,
                         float* __restrict__ gw) {
    int warp = (blockIdx.x * blockDim.x + threadIdx.x) >> 5;
    int lane = threadIdx.x & 31;
    if (warp >= BATCH) return;
    const float4* f4 = (const float4*)(feat + (size_t)warp * DIN);
    float acc[10];
#pragma unroll
    for (int e = 0; e < 10; e++) acc[e] = 0.0f;
#pragma unroll 5
    for (int it = 0; it < 25; it++) {
        int k4 = it * 32 + lane;
        float4 fv = f4[k4];
#pragma unroll
        for (int e = 0; e < 10; e++) {
            float4 wv = ((const float4*)(wgT + e * DIN))[k4];
            acc[e] += fv.x * wv.x + fv.y * wv.y + fv.z * wv.z + fv.w * wv.w;
        }
    }
#pragma unroll
    for (int off = 16; off; off >>= 1)
#pragma unroll
        for (int e = 0; e < 10; e++)
            acc[e] += __shfl_down_sync(0xFFFFFFFFu, acc[e], off);

    if (lane == 0) {
        float gate[NEXP];
#pragma unroll
        for (int e = 0; e < NEXP; e++) {
            float g = acc[e] + bg[e];
            float s = 1.0f / (1.0f + expf(-(acc[5 + e] + bgl[e])));
            gate[e] = g * s;
        }
        float v0 = -1e30f, v1 = -1e30f, v2 = -1e30f;
        int i0 = 0, i1 = 0, i2 = 0;
#pragma unroll
        for (int e = 0; e < NEXP; e++) {
            float g = gate[e];
            if (g > v0)      { v2 = v1; i2 = i1; v1 = v0; i1 = i0; v0 = g; i0 = e; }
            else if (g > v1) { v2 = v1; i2 = i1; v1 = g;  i1 = e; }
            else if (g > v2) { v2 = g;  i2 = e; }
        }
        float e1 = expf(v1 - v0);
        float e2 = expf(v2 - v0);
        float inv = 1.0f / (1.0f + e1 + e2);
        float wout[NEXP];
#pragma unroll
        for (int e = 0; e < NEXP; e++) wout[e] = 0.0f;
        wout[i0] = inv; wout[i1] = e1 * inv; wout[i2] = e2 * inv;
#pragma unroll
        for (int e = 0; e < NEXP; e++) gw[warp * NEXP + e] = wout[e];
    }
}

// ===== Kernel 4: e1 = tanh(feat @ W1e + b1e) — HMMA, 3-stage cp.async pipeline ==
#define BKC   32
#define NTC   (DIN / BKC)          // 100 k-chunks
#define PITCH 80                   // bytes per 32-bf16 row
#define G1_TILE (128 * PITCH)      // 10240 per operand stage
#define G1_SMEM (6 * G1_TILE)      // 3 stages x (A + B) = 61440
__global__ void __launch_bounds__(256)
k_gemm1_mma(const __nv_bfloat16* __restrict__ A,
            const __nv_bfloat16* __restrict__ Bt,
            const float* __restrict__ b1e,
            __nv_bfloat16* __restrict__ E1bf) {     // [8192,640] bf16
    extern __shared__ __align__(128) unsigned char dsm[];
    uint32_t sA0 = smem_u32(dsm);
    uint32_t sB0 = sA0 + 3 * G1_TILE;

    int tid = threadIdx.x;
    int w = tid >> 5, lane = tid & 31;
    int wm = w & 3, wn = w >> 2;
    int mb = blockIdx.x, e = blockIdx.y;

    const __nv_bfloat16* Ab = A  + (size_t)(mb * 128) * DIN;
    const __nv_bfloat16* Bb = Bt + (size_t)e * DH * DIN;

    float acc[2][8][4];
#pragma unroll
    for (int i = 0; i < 2; i++)
#pragma unroll
        for (int j = 0; j < 8; j++)
#pragma unroll
            for (int q = 0; q < 4; q++) acc[i][j][q] = 0.0f;

    int lr = tid >> 1;
    int lc = (tid & 1) * 2;
    auto load_tile = [&](int t, int s) {
        int k0 = t * BKC;
        uint32_t aD = sA0 + s * G1_TILE + lr * PITCH + lc * 16;
        uint32_t bD = sB0 + s * G1_TILE + lr * PITCH + lc * 16;
        const __nv_bfloat16* aS = Ab + (size_t)lr * DIN + k0 + lc * 8;
        const __nv_bfloat16* bS = Bb + (size_t)lr * DIN + k0 + lc * 8;
        cp_async16(aD,      aS);
        cp_async16(aD + 16, aS + 8);
        cp_async16(bD,      bS);
        cp_async16(bD + 16, bS + 8);
    };

    load_tile(0, 0); CP_COMMIT();
    load_tile(1, 1); CP_COMMIT();

    int aRow = (lane & 7) + ((lane >> 3) & 1) * 8;
    int aKb  = (lane >> 4) * 16;
    int bRow = (lane & 7) + (lane >> 4) * 8;
    int bKb  = ((lane >> 3) & 1) * 16;

    int s = 0;                     // stage = t % 3
    for (int t = 0; t < NTC; t++) {
        CP_WAIT(1);                // tile t's group complete (t+1 may pend)
        __syncthreads();           // everyone done computing t-1 before refilling
        if (t + 2 < NTC) {
            int s2 = s + 2; if (s2 >= 3) s2 -= 3;
            load_tile(t + 2, s2);
        }
        CP_COMMIT();               // always commit (uniform group accounting)

        uint32_t aT = sA0 + s * G1_TILE;
        uint32_t bT = sB0 + s * G1_TILE;
#pragma unroll
        for (int ks = 0; ks < 2; ks++) {
            uint32_t a[2][4], b[8][2];
#pragma unroll
            for (int i = 0; i < 2; i++) {
                uint32_t addr = aT + (wm * 32 + i * 16 + aRow) * PITCH + ks * 32 + aKb;
                ldsm_x4(addr, a[i][0], a[i][1], a[i][2], a[i][3]);
            }
#pragma unroll
            for (int j2 = 0; j2 < 4; j2++) {
                uint32_t addr = bT + (wn * 64 + j2 * 16 + bRow) * PITCH + ks * 32 + bKb;
                ldsm_x4(addr, b[2 * j2][0], b[2 * j2][1], b[2 * j2 + 1][0], b[2 * j2 + 1][1]);
            }
#pragma unroll
            for (int i = 0; i < 2; i++)
#pragma unroll
                for (int j = 0; j < 8; j++)
                    mma_bf16(acc[i][j], a[i], b[j]);
        }
        if (++s == 3) s = 0;
    }

    const float* bias = b1e + e * DH;
    int qr = lane >> 2;
    int qc = (lane & 3) * 2;
#pragma unroll
    for (int i = 0; i < 2; i++) {
        int m0 = mb * 128 + wm * 32 + i * 16 + qr;
#pragma unroll
        for (int j = 0; j < 8; j++) {
            int c = wn * 64 + j * 8 + qc;
            float b0 = __ldg(&bias[c]);
            float b1 = __ldg(&bias[c + 1]);
            uint32_t p0 = bf16pack(tanhf(acc[i][j][0] + b0), tanhf(acc[i][j][1] + b1));
            uint32_t p1 = bf16pack(tanhf(acc[i][j][2] + b0), tanhf(acc[i][j][3] + b1));
            *(uint32_t*)(E1bf + (size_t)m0 * (NEXP * DH) + e * DH + c) = p0;
            *(uint32_t*)(E1bf + (size_t)(m0 + 8) * (NEXP * DH) + e * DH + c) = p1;
        }
    }
}

// ====== Kernel 5: expert-2 via HMMA bf16 + weighted combine + head + softmax ====
#define E2P   272                       // smem row pitch bytes (136 bf16)
#define E2_SA  0                        // A: 32 x 136 bf16 = 8704
#define E2_SB  8704                     // B: 128 x 136 bf16 = 34816
#define E2_MOE 43520                    // 32 x 128 f32 = 16384
#define E2_WS  59904                    // 1280 f32 = 5120
#define E2_GW  65024                    // 160 f32 = 640
#define E2_LOG 65664                    // 320 f32 = 1280
#define E2_SMEM 66944
__global__ void __launch_bounds__(256)
k_expert2_mma(const __nv_bfloat16* __restrict__ E1bf,   // [8192,640]
              const __nv_bfloat16* __restrict__ W2t,    // [5][g][h]
              const float* __restrict__ b2e,            // [5,128]
              const float* __restrict__ gw,             // [8192,5]
              const float* __restrict__ Ws,             // [128,10]
              const float* __restrict__ bs,             // [10]
              float* __restrict__ out) {                // [8192,10]
    extern __shared__ __align__(16) unsigned char dsm[];
    uint32_t sb = smem_u32(dsm);
    int tid = threadIdx.x;
    int w = tid >> 5, lane = tid & 31;
    int b0 = blockIdx.x * 32;

    float* s_ws  = (float*)(dsm + E2_WS);
    float* s_gw  = (float*)(dsm + E2_GW);
    float* s_moe = (float*)(dsm + E2_MOE);
    float* s_log = (float*)(dsm + E2_LOG);

    for (int i = tid; i < 1280; i += 256) s_ws[i] = Ws[i];
    for (int i = tid; i < 160; i += 256)  s_gw[i] = gw[b0 * NEXP + i];

    int aRow = (lane & 7) + ((lane >> 3) & 1) * 8;
    int aKb  = (lane >> 4) * 16;
    int bRow = (lane & 7) + (lane >> 4) * 8 + w * 16;
    int bKb  = ((lane >> 3) & 1) * 16;

    float moe[2][2][4];
#pragma unroll
    for (int i = 0; i < 2; i++)
#pragma unroll
        for (int j = 0; j < 2; j++)
#pragma unroll
            for (int q = 0; q < 4; q++) moe[i][j][q] = 0.0f;

    for (int e = 0; e < NEXP; e++) {
        __syncthreads();   // prior compute done before overwriting tiles
        for (int c = tid; c < 512; c += 256) {
            int r = c >> 4, ck = c & 15;
            cp_async16(sb + E2_SA + r * E2P + ck * 16,
                       E1bf + (size_t)(b0 + r) * (NEXP * DH) + e * DH + ck * 8);
        }
        for (int c = tid; c < 2048; c += 256) {
            int r = c >> 4, ck = c & 15;
            cp_async16(sb + E2_SB + r * E2P + ck * 16,
                       W2t + (size_t)e * DH * DH + r * DH + ck * 8);
        }
        CP_COMMIT(); CP_WAIT(0);
        __syncthreads();

        float acc[2][2][4];
#pragma unroll
        for (int i = 0; i < 2; i++)
#pragma unroll
            for (int j = 0; j < 2; j++)
#pragma unroll
                for (int q = 0; q < 4; q++) acc[i][j][q] = 0.0f;

#pragma unroll
        for (int k16 = 0; k16 < 8; k16++) {
            uint32_t a[2][4], b[2][2];
#pragma unroll
            for (int i = 0; i < 2; i++)
                ldsm_x4(sb + E2_SA + (i * 16 + aRow) * E2P + k16 * 32 + aKb,
                        a[i][0], a[i][1], a[i][2], a[i][3]);
            ldsm_x4(sb + E2_SB + bRow * E2P + k16 * 32 + bKb,
                    b[0][0], b[0][1], b[1][0], b[1][1]);
#pragma unroll
            for (int i = 0; i < 2; i++)
#pragma unroll
                for (int j = 0; j < 2; j++)
                    mma_bf16(acc[i][j], a[i], b[j]);
        }

#pragma unroll
        for (int i = 0; i < 2; i++)
#pragma unroll
            for (int j = 0; j < 2; j++)
#pragma unroll
                for (int q = 0; q < 4; q++) {
                    int row = i * 16 + (lane >> 2) + ((q >> 1) ? 8 : 0);
                    int g = w * 16 + j * 8 + (lane & 3) * 2 + (q & 1);
                    float pre = acc[i][j][q] + __ldg(&b2e[e * DH + g]);
                    moe[i][j][q] += s_gw[row * NEXP + e] * tanhf(pre);
                }
    }

    __syncthreads();
#pragma unroll
    for (int i = 0; i < 2; i++)
#pragma unroll
        for (int j = 0; j < 2; j++)
#pragma unroll
            for (int q = 0; q < 4; q++) {
                int row = i * 16 + (lane >> 2) + ((q >> 1) ? 8 : 0);
                int g = w * 16 + j * 8 + (lane & 3) * 2 + (q & 1);
                s_moe[row * DH + g] = moe[i][j][q];
            }
    __syncthreads();

    for (int i = tid; i < 320; i += 256) {
        int r = i / 10, c = i % 10;
        float a = __ldg(&bs[c]);
#pragma unroll 16
        for (int hh = 0; hh < 128; hh++)
            a += s_moe[r * DH + hh] * s_ws[hh * 10 + c];
        s_log[r * 10 + c] = a;
    }
    __syncthreads();
    if (tid < 32) {
        int r = tid;
        float m = -1e30f;
#pragma unroll
        for (int c = 0; c < 10; c++) m = fmaxf(m, s_log[r * 10 + c]);
        float ex[10], ssum = 0.0f;
#pragma unroll
        for (int c = 0; c < 10; c++) { ex[c] = expf(s_log[r * 10 + c] - m); ssum += ex[c]; }
        float inv = 1.0f / ssum;
        float* orow = out + (size_t)(b0 + r) * 10;
#pragma unroll
        for (int c = 0; c < 10; c++) orow[c] = ex[c] * inv;
    }
}

// =============================== launcher =======================================
extern "C" void kernel_launch(void* const* d_in, const int* in_sizes, int n_in,
                              void* d_out, int out_size) {
    const float* x       = (const float*)d_in[0];
    const float* conv1_w = (const float*)d_in[1];
    const float* conv1_b = (const float*)d_in[2];
    const float* conv2_w = (const float*)d_in[3];
    const float* conv2_b = (const float*)d_in[4];
    const float* Wg      = (const float*)d_in[5];
    const float* bg      = (const float*)d_in[6];
    const float* Wglu    = (const float*)d_in[7];
    const float* bglu    = (const float*)d_in[8];
    const float* W1e     = (const float*)d_in[9];
    const float* b1e     = (const float*)d_in[10];
    const float* W2e     = (const float*)d_in[11];
    const float* b2e     = (const float*)d_in[12];
    const float* Ws      = (const float*)d_in[13];
    const float* bs      = (const float*)d_in[14];
    float* out = (float*)d_out;

    float *feat, *wgT, *gwp;
    __nv_bfloat16 *poolh, *pooll, *featbf, *w1t, *w2t, *e1bf;
    cudaGetSymbolAddress((void**)&poolh,  g_poolt_h);
    cudaGetSymbolAddress((void**)&pooll,  g_poolt_l);
    cudaGetSymbolAddress((void**)&feat,   g_feat);
    cudaGetSymbolAddress((void**)&featbf, g_featbf);
    cudaGetSymbolAddress((void**)&w1t,    g_w1t);
    cudaGetSymbolAddress((void**)&w2t,    g_w2t);
    cudaGetSymbolAddress((void**)&wgT,    g_wgT);
    cudaGetSymbolAddress((void**)&gwp,    g_gw);
    cudaGetSymbolAddress((void**)&e1bf,   g_e1bf);

    cudaFuncSetAttribute(k_conv2_mma,   cudaFuncAttributeMaxDynamicSharedMemorySize, C2_SMEM);
    cudaFuncSetAttribute(k_gemm1_mma,   cudaFuncAttributeMaxDynamicSharedMemorySize, G1_SMEM);
    cudaFuncSetAttribute(k_expert2_mma, cudaFuncAttributeMaxDynamicSharedMemorySize, E2_SMEM);

    k_wgt<<<(10 * DIN + 255) / 256, 256>>>(Wg, Wglu, wgT);
    dim3 gW(DIN / 32, DH / 32, NEXP);
    k_w1_convert<<<gW, dim3(32, 8)>>>(W1e, w1t);
    dim3 gW2(DH / 32, DH / 32, NEXP);
    k_w2_convert<<<gW2, dim3(32, 8)>>>(W2e, w2t);
    k_conv1_mma<<<BATCH, 192>>>(x, conv1_w, conv1_b, poolh, pooll);
    k_conv2_mma<<<BATCH / 2, 256, C2_SMEM>>>(poolh, pooll, conv2_w, conv2_b, feat, featbf);
    k_router<<<BATCH / 8, 256>>>(feat, wgT, bg, bglu, gwp);
    dim3 g4(BATCH / 128, NEXP);
    k_gemm1_mma<<<g4, 256, G1_SMEM>>>(featbf, w1t, b1e, e1bf);
    k_expert2_mma<<<BATCH / 32, 256, E2_SMEM>>>(e1bf, w2t, b2e, gwp, Ws, bs, out);
}